// round 9
// baseline (speedup 1.0000x reference)
#include <cuda_runtime.h>
#include <cuda_fp16.h>
#include <cstdint>

// Problem constants
#define HH     1024
#define BB     4
#define SS     1024
#define NHEADS 16
#define DHEAD  64
#define MTOT   (BB * SS)

// fp16 copies of GEMM inputs.
__device__ __align__(16) __half g_xh[3][(size_t)MTOT * HH];
__device__ __align__(16) __half g_wh[3][(size_t)HH * HH];

// GEMM outputs for attention: Q (pre-scaled by 0.125*log2e), K, V in fp16.
__device__ __align__(16) __half g_qh[(size_t)MTOT * HH];
__device__ __align__(16) __half g_kh[(size_t)MTOT * HH];
__device__ __align__(16) __half g_vh[(size_t)MTOT * HH];

#define SCLQ 0.18033688f   // 0.125 * log2(e)

// ---------------------------------------------------------------------------
// helpers
// ---------------------------------------------------------------------------
static __device__ __forceinline__ uint32_t smem_u32(const void* p) {
    uint32_t a;
    asm("{ .reg .u64 t; cvta.to.shared.u64 t, %1; cvt.u32.u64 %0, t; }"
        : "=r"(a) : "l"(p));
    return a;
}
static __device__ __forceinline__ uint32_t pack2h(float x, float y) {
    __half2 h = __floats2half2_rn(x, y);
    return *reinterpret_cast<uint32_t*>(&h);
}
static __device__ __forceinline__ float2 unpack2h(uint32_t u) {
    __half2 h = *reinterpret_cast<__half2*>(&u);
    return __half22float2(h);
}
static __device__ __forceinline__ void cp16(uint32_t saddr, const void* g) {
    asm volatile("cp.async.cg.shared.global [%0], [%1], 16;"
                 :: "r"(saddr), "l"(g) : "memory");
}
#define CP_COMMIT() asm volatile("cp.async.commit_group;" ::: "memory")

static __device__ __forceinline__ void mma_f16(float* c, const uint32_t* a, const uint32_t* b) {
    asm volatile(
        "mma.sync.aligned.m16n8k16.row.col.f32.f16.f16.f32 "
        "{%0,%1,%2,%3}, {%4,%5,%6,%7}, {%8,%9}, {%0,%1,%2,%3};"
        : "+f"(c[0]), "+f"(c[1]), "+f"(c[2]), "+f"(c[3])
        : "r"(a[0]), "r"(a[1]), "r"(a[2]), "r"(a[3]), "r"(b[0]), "r"(b[1]));
}
// fp16-accumulate variant
static __device__ __forceinline__ void mma_f16h(uint32_t* c, const uint32_t* a, const uint32_t* b) {
    asm volatile(
        "mma.sync.aligned.m16n8k16.row.col.f16.f16.f16.f16 "
        "{%0,%1}, {%2,%3,%4,%5}, {%6,%7}, {%0,%1};"
        : "+r"(c[0]), "+r"(c[1])
        : "r"(a[0]), "r"(a[1]), "r"(a[2]), "r"(a[3]), "r"(b[0]), "r"(b[1]));
}
static __device__ __forceinline__ void ldsm4(uint32_t* r, uint32_t saddr) {
    asm volatile("ldmatrix.sync.aligned.m8n8.x4.shared.b16 {%0,%1,%2,%3}, [%4];"
                 : "=r"(r[0]), "=r"(r[1]), "=r"(r[2]), "=r"(r[3]) : "r"(saddr));
}
static __device__ __forceinline__ void ldsm4t(uint32_t* r, uint32_t saddr) {
    asm volatile("ldmatrix.sync.aligned.m8n8.x4.trans.shared.b16 {%0,%1,%2,%3}, [%4];"
                 : "=r"(r[0]), "=r"(r[1]), "=r"(r[2]), "=r"(r[3]) : "r"(saddr));
}
static __device__ __forceinline__ float ex2(float x) {
    float y; asm("ex2.approx.f32 %0, %1;" : "=f"(y) : "f"(x)); return y;
}

// ---------------------------------------------------------------------------
// fp32 -> fp16 convert: 4 float4 per thread (fewer blocks, better issue).
// ---------------------------------------------------------------------------
__global__ void convert_h(const float4* __restrict__ s0, const float4* __restrict__ s1,
                          const float4* __restrict__ s2, const float4* __restrict__ s3,
                          const float4* __restrict__ s4, const float4* __restrict__ s5,
                          int n4x, int n4w)
{
    const int m = blockIdx.y;
    const int n4 = (m < 3) ? n4x : n4w;
    const int i0 = (blockIdx.x * 256 + threadIdx.x) * 4;
    if (i0 >= n4) return;
    const float4* src = (m == 0) ? s0 : (m == 1) ? s1 : (m == 2) ? s2
                       : (m == 3) ? s3 : (m == 4) ? s4 : s5;
    uint2* dst = (m < 3) ? (uint2*)g_xh[m] : (uint2*)g_wh[m - 3];
#pragma unroll
    for (int j = 0; j < 4; j++) {
        float4 v = src[i0 + j];
        dst[i0 + j] = make_uint2(pack2h(v.x, v.y), pack2h(v.z, v.w));
    }
}

// ---------------------------------------------------------------------------
// Tensor-core GEMM, fp16 ACCUMULATORS with per-stage fp32 promotion:
//   relu(X @ W^T + b) -> fp16.
// CTA tile 128x64, 8 warps (2M x 4N), warp tile 64x16. K staged 64,
// cp.async triple-buffered ring, one __syncthreads per stage.
// Each stage: 4 k16 mma_f16h into fp16 D-frags, then promote into fp32 regs
// (bounds fp16 accumulation error to 64 terms per promotion).
// ---------------------------------------------------------------------------
#define GST   144                    // row stride (bytes)
#define GAT   (128 * GST)            // A tile 18432 B
#define GBT   (64 * GST)             // B tile  9216 B
#define GSTG  (GAT + GBT)            // 27648 B per stage
#define GNST  (HH / 64)              // 16 k-stages
#define GEMM_SMEM (3 * GSTG)         // 82944 B -> 2 CTA/SM

__global__ void __launch_bounds__(256, 2) gemm_mma(
    const float* __restrict__ bq, const float* __restrict__ bk, const float* __restrict__ bv)
{
    extern __shared__ char smc[];
    const int mat = blockIdx.z;
    const float* bias = (mat == 0) ? bq : ((mat == 1) ? bk : bv);

    const int tid  = threadIdx.x;
    const int lane = tid & 31;
    const int wid  = tid >> 5;
    const int wm   = wid & 1;           // 2 M-warps
    const int wn   = wid >> 1;          // 4 N-warps
    const int bm   = blockIdx.y * 128;
    const int bn   = blockIdx.x * 64;

    const __half* Ah = g_xh[mat] + (size_t)bm * HH;
    const __half* Bh = g_wh[mat] + (size_t)bn * HH;

    const uint32_t smem_base = smem_u32(smc);

    auto issue_stage = [&](int s, int buf) {
        const uint32_t sb = smem_base + (uint32_t)buf * GSTG;
        const int k0 = s * 64;
#pragma unroll
        for (int i = 0; i < 4; i++) {            // A: 128 rows x 8 chunks
            const int idx = tid + i * 256;
            const int row = idx >> 3;
            const int q   = idx & 7;
            cp16(sb + (uint32_t)(row * GST + q * 16),
                 Ah + (size_t)row * HH + k0 + q * 8);
        }
#pragma unroll
        for (int i = 0; i < 2; i++) {            // B: 64 rows x 8 chunks
            const int idx = tid + i * 256;
            const int row = idx >> 3;
            const int q   = idx & 7;
            cp16(sb + GAT + (uint32_t)(row * GST + q * 16),
                 Bh + (size_t)row * HH + k0 + q * 8);
        }
    };

    float acc[4][2][4];
#pragma unroll
    for (int i = 0; i < 4; i++)
#pragma unroll
        for (int j = 0; j < 2; j++)
#pragma unroll
            for (int k = 0; k < 4; k++) acc[i][j][k] = 0.f;

    issue_stage(0, 0); CP_COMMIT();
    issue_stage(1, 1); CP_COMMIT();

    const int arow = wm * 64 + ((lane >> 3) & 1) * 8 + (lane & 7);
    const int acol = (lane >> 4) * 8;
    const int brow = wn * 16 + (lane & 15);
    const int bcol = (lane >> 4) * 8;

    int cur = 0;
    for (int s = 0; s < GNST; s++) {
        if (s + 1 < GNST) { asm volatile("cp.async.wait_group 1;" ::: "memory"); }
        else              { asm volatile("cp.async.wait_group 0;" ::: "memory"); }
        __syncthreads();

        if (s + 2 < GNST) {
            int nb = cur + 2; if (nb >= 3) nb -= 3;
            issue_stage(s + 2, nb);
            CP_COMMIT();
        }

        const uint32_t sA = smem_base + (uint32_t)cur * GSTG;
        const uint32_t sB = sA + GAT;

        uint32_t accH[4][2][2];
#pragma unroll
        for (int i = 0; i < 4; i++)
#pragma unroll
            for (int j = 0; j < 2; j++) { accH[i][j][0] = 0u; accH[i][j][1] = 0u; }

#pragma unroll
        for (int t = 0; t < 4; t++) {
            uint32_t Af[4][4];
#pragma unroll
            for (int mf = 0; mf < 4; mf++)
                ldsm4(Af[mf], sA + (arow + mf * 16) * GST + (t * 16 + acol) * 2);
            uint32_t kh[4];
            ldsm4(kh, sB + brow * GST + (t * 16 + bcol) * 2);
            uint32_t Bf0[2] = {kh[0], kh[2]};
            uint32_t Bf1[2] = {kh[1], kh[3]};
#pragma unroll
            for (int mf = 0; mf < 4; mf++) {
                mma_f16h(accH[mf][0], Af[mf], Bf0);
                mma_f16h(accH[mf][1], Af[mf], Bf1);
            }
        }

        // promote stage partials into fp32
#pragma unroll
        for (int mf = 0; mf < 4; mf++)
#pragma unroll
            for (int nf = 0; nf < 2; nf++) {
                float2 a = unpack2h(accH[mf][nf][0]);
                float2 c = unpack2h(accH[mf][nf][1]);
                acc[mf][nf][0] += a.x;
                acc[mf][nf][1] += a.y;
                acc[mf][nf][2] += c.x;
                acc[mf][nf][3] += c.y;
            }

        cur = (cur + 1 == 3) ? 0 : cur + 1;
    }

    // Epilogue: bias + relu (+SCLQ for Q), write fp16.
    const float sc = (mat == 0) ? SCLQ : 1.0f;
    uint32_t* ph = (mat == 0) ? (uint32_t*)g_qh : ((mat == 1) ? (uint32_t*)g_kh : (uint32_t*)g_vh);

#pragma unroll
    for (int nf = 0; nf < 2; nf++) {
        const int col = bn + wn * 16 + nf * 8 + (lane & 3) * 2;
        const float2 bs = *(const float2*)&bias[col];
#pragma unroll
        for (int mf = 0; mf < 4; mf++) {
            const int row0 = bm + wm * 64 + mf * 16 + (lane >> 2);
            float v0 = fmaxf(acc[mf][nf][0] + bs.x, 0.f) * sc;
            float v1 = fmaxf(acc[mf][nf][1] + bs.y, 0.f) * sc;
            float v2 = fmaxf(acc[mf][nf][2] + bs.x, 0.f) * sc;
            float v3 = fmaxf(acc[mf][nf][3] + bs.y, 0.f) * sc;
            ph[((size_t)row0 * HH + col) >> 1]       = pack2h(v0, v1);
            ph[((size_t)(row0 + 8) * HH + col) >> 1] = pack2h(v2, v3);
        }
    }
}

// ---------------------------------------------------------------------------
// Tensor-core flash attention (unchanged from R8): max-free softmax,
// kv-tile 64, fp16-acc QK^T (bit-exact repack into P A-frags), fp32-acc PV.
// ---------------------------------------------------------------------------
#define QB      64
#define KRST    144
#define KVT     64
#define KVOFF   (KVT * KRST)
#define KBUF    (2 * KVOFF)
#define ATT_SMEM (2 * KBUF)
#define NKV     (SS / KVT)

__global__ void __launch_bounds__(128, 4) attn_tc(
    const float* __restrict__ masks,
    const float* __restrict__ query,
    float* __restrict__ out)
{
    extern __shared__ char sma[];
    const uint32_t smb = smem_u32(sma);

    const int b    = blockIdx.z;
    const int n    = blockIdx.y;
    const int q0   = blockIdx.x * QB;
    const int tid  = threadIdx.x;
    const int lane = tid & 31;
    const int wid  = tid >> 5;
    const int hc   = n * DHEAD;

#pragma unroll
    for (int i = 0; i < 4; i++) {
        const int idx = tid + i * 128;
        const int row = idx >> 3, qq = idx & 7;
        cp16(smb + row * KRST + qq * 16,
             g_qh + (size_t)(b * SS + q0 + row) * HH + hc + qq * 8);
    }
    CP_COMMIT();
    asm volatile("cp.async.wait_group 0;" ::: "memory");
    __syncthreads();

    uint32_t qh[4][4];
    {
        const int arow = wid * 16 + ((lane >> 3) & 1) * 8 + (lane & 7);
        const int acol = (lane >> 4) * 8;
#pragma unroll
        for (int t = 0; t < 4; t++)
            ldsm4(qh[t], smb + arow * KRST + (16 * t + acol) * 2);
    }
    __syncthreads();

    auto issue_kv = [&](int s) {
        const uint32_t sb = smb + (uint32_t)((s & 1) * KBUF);
        const size_t tokbase = (size_t)(b * SS + s * KVT);
#pragma unroll
        for (int i = 0; i < 4; i++) {
            const int idx = tid + i * 128;
            const int row = idx >> 3, qq = idx & 7;
            const uint32_t soff = row * KRST + qq * 16;
            const size_t goff = (tokbase + row) * HH + hc + qq * 8;
            cp16(sb + soff, g_kh + goff);
            cp16(sb + KVOFF + soff, g_vh + goff);
        }
    };
    issue_kv(0); CP_COMMIT();
    issue_kv(1); CP_COMMIT();

    float O[8][4];
    float l0 = 0.f, l1 = 0.f;
#pragma unroll
    for (int i = 0; i < 8; i++)
#pragma unroll
        for (int j = 0; j < 4; j++) O[i][j] = 0.f;

    const int brow = lane & 15;
    const int bcol = (lane >> 4) * 8;

    for (int kb = 0; kb < NKV; kb++) {
        if (kb + 1 < NKV) { asm volatile("cp.async.wait_group 1;" ::: "memory"); }
        else              { asm volatile("cp.async.wait_group 0;" ::: "memory"); }
        __syncthreads();

        const uint32_t sb = smb + (uint32_t)((kb & 1) * KBUF);

        uint32_t Sh[8][2];
#pragma unroll
        for (int i = 0; i < 8; i++) { Sh[i][0] = 0u; Sh[i][1] = 0u; }

#pragma unroll
        for (int t = 0; t < 4; t++) {
#pragma unroll
            for (int j = 0; j < 4; j++) {
                uint32_t kh[4], bf[2];
                ldsm4(kh, sb + (16 * j + brow) * KRST + (16 * t + bcol) * 2);
                bf[0] = kh[0]; bf[1] = kh[2];
                mma_f16h(Sh[2 * j], qh[t], bf);
                bf[0] = kh[1]; bf[1] = kh[3];
                mma_f16h(Sh[2 * j + 1], qh[t], bf);
            }
        }

#pragma unroll
        for (int i = 0; i < 8; i++) {
            float2 a = unpack2h(Sh[i][0]);
            float2 c = unpack2h(Sh[i][1]);
            float e0 = ex2(a.x), e1 = ex2(a.y);
            float e2 = ex2(c.x), e3 = ex2(c.y);
            l0 += e0 + e1;
            l1 += e2 + e3;
            Sh[i][0] = pack2h(e0, e1);
            Sh[i][1] = pack2h(e2, e3);
        }

#pragma unroll
        for (int i = 0; i < 4; i++) {
            uint32_t Pa4[4] = {Sh[2 * i][0], Sh[2 * i][1],
                               Sh[2 * i + 1][0], Sh[2 * i + 1][1]};
#pragma unroll
            for (int t4 = 0; t4 < 4; t4++) {
                uint32_t v[4];
                ldsm4t(v, sb + KVOFF + (16 * i + brow) * KRST + (16 * t4 + bcol) * 2);
                mma_f16(O[2 * t4], Pa4, v);
                mma_f16(O[2 * t4 + 1], Pa4, v + 2);
            }
        }

        __syncthreads();
        if (kb + 2 < NKV) { issue_kv(kb + 2); CP_COMMIT(); }
    }

    l0 += __shfl_xor_sync(0xffffffffu, l0, 1);
    l0 += __shfl_xor_sync(0xffffffffu, l0, 2);
    l1 += __shfl_xor_sync(0xffffffffu, l1, 1);
    l1 += __shfl_xor_sync(0xffffffffu, l1, 2);

    const int qr0 = q0 + wid * 16 + (lane >> 2);
    const int qr1 = qr0 + 8;
    const float inv0 = masks[b * SS + qr0] / l0;
    const float inv1 = masks[b * SS + qr1] / l1;
#pragma unroll
    for (int nf = 0; nf < 8; nf++) {
        const int col = hc + nf * 8 + (lane & 3) * 2;
        const size_t o0 = (size_t)(b * SS + qr0) * HH + col;
        const size_t o1 = (size_t)(b * SS + qr1) * HH + col;
        float2 r0 = *(const float2*)&query[o0];
        float2 r1 = *(const float2*)&query[o1];
        r0.x = fmaf(O[nf][0], inv0, r0.x);
        r0.y = fmaf(O[nf][1], inv0, r0.y);
        r1.x = fmaf(O[nf][2], inv1, r1.x);
        r1.y = fmaf(O[nf][3], inv1, r1.y);
        *(float2*)&out[o0] = r0;
        *(float2*)&out[o1] = r1;
    }
}

// ---------------------------------------------------------------------------
extern "C" void kernel_launch(void* const* d_in, const int* in_sizes, int n_in,
                              void* d_out, int out_size)
{
    (void)in_sizes; (void)n_in; (void)out_size;
    const float* query = (const float*)d_in[0];
    const float* key   = (const float*)d_in[1];
    const float* value = (const float*)d_in[2];
    const float* masks = (const float*)d_in[3];
    const float* Wq    = (const float*)d_in[4];
    const float* bq    = (const float*)d_in[5];
    const float* Wk    = (const float*)d_in[6];
    const float* bk    = (const float*)d_in[7];
    const float* Wv    = (const float*)d_in[8];
    const float* bv    = (const float*)d_in[9];
    float* out = (float*)d_out;

    const int n4x = MTOT * HH / 4;
    const int n4w = HH * HH / 4;
    convert_h<<<dim3(n4x / 1024, 6), 256>>>(
        (const float4*)query, (const float4*)key, (const float4*)value,
        (const float4*)Wq, (const float4*)Wk, (const float4*)Wv, n4x, n4w);

    cudaFuncSetAttribute(gemm_mma, cudaFuncAttributeMaxDynamicSharedMemorySize, GEMM_SMEM);
    gemm_mma<<<dim3(HH / 64, MTOT / 128, 3), 256, GEMM_SMEM>>>(bq, bk, bv);

    cudaFuncSetAttribute(attn_tc, cudaFuncAttributeMaxDynamicSharedMemorySize, ATT_SMEM);
    attn_tc<<<dim3(SS / QB, NHEADS, BB), 128, ATT_SMEM>>>(masks, query, out);
}

// round 10
// speedup vs baseline: 1.0292x; 1.0292x over previous
#include <cuda_runtime.h>
#include <cuda_fp16.h>
#include <cstdint>

// Problem constants
#define HH     1024
#define BB     4
#define SS     1024
#define NHEADS 16
#define DHEAD  64
#define MTOT   (BB * SS)

// fp16 copies of GEMM inputs.
__device__ __align__(16) __half g_xh[3][(size_t)MTOT * HH];
__device__ __align__(16) __half g_wh[3][(size_t)HH * HH];

// GEMM outputs for attention: Q (pre-scaled by 0.125*log2e), K, V in fp16.
__device__ __align__(16) __half g_qh[(size_t)MTOT * HH];
__device__ __align__(16) __half g_kh[(size_t)MTOT * HH];
__device__ __align__(16) __half g_vh[(size_t)MTOT * HH];

#define SCLQ 0.18033688f   // 0.125 * log2(e)

// ---------------------------------------------------------------------------
// helpers
// ---------------------------------------------------------------------------
static __device__ __forceinline__ uint32_t smem_u32(const void* p) {
    uint32_t a;
    asm("{ .reg .u64 t; cvta.to.shared.u64 t, %1; cvt.u32.u64 %0, t; }"
        : "=r"(a) : "l"(p));
    return a;
}
static __device__ __forceinline__ uint32_t pack2h(float x, float y) {
    __half2 h = __floats2half2_rn(x, y);
    return *reinterpret_cast<uint32_t*>(&h);
}
static __device__ __forceinline__ float2 unpack2h(uint32_t u) {
    __half2 h = *reinterpret_cast<__half2*>(&u);
    return __half22float2(h);
}
static __device__ __forceinline__ void cp16(uint32_t saddr, const void* g) {
    asm volatile("cp.async.cg.shared.global [%0], [%1], 16;"
                 :: "r"(saddr), "l"(g) : "memory");
}
#define CP_COMMIT() asm volatile("cp.async.commit_group;" ::: "memory")

static __device__ __forceinline__ void mma_f16(float* c, const uint32_t* a, const uint32_t* b) {
    asm volatile(
        "mma.sync.aligned.m16n8k16.row.col.f32.f16.f16.f32 "
        "{%0,%1,%2,%3}, {%4,%5,%6,%7}, {%8,%9}, {%0,%1,%2,%3};"
        : "+f"(c[0]), "+f"(c[1]), "+f"(c[2]), "+f"(c[3])
        : "r"(a[0]), "r"(a[1]), "r"(a[2]), "r"(a[3]), "r"(b[0]), "r"(b[1]));
}
// fp16-accumulate variant (QK^T only — logits small, 4 k-steps)
static __device__ __forceinline__ void mma_f16h(uint32_t* c, const uint32_t* a, const uint32_t* b) {
    asm volatile(
        "mma.sync.aligned.m16n8k16.row.col.f16.f16.f16.f16 "
        "{%0,%1}, {%2,%3,%4,%5}, {%6,%7}, {%0,%1};"
        : "+r"(c[0]), "+r"(c[1])
        : "r"(a[0]), "r"(a[1]), "r"(a[2]), "r"(a[3]), "r"(b[0]), "r"(b[1]));
}
static __device__ __forceinline__ void ldsm4(uint32_t* r, uint32_t saddr) {
    asm volatile("ldmatrix.sync.aligned.m8n8.x4.shared.b16 {%0,%1,%2,%3}, [%4];"
                 : "=r"(r[0]), "=r"(r[1]), "=r"(r[2]), "=r"(r[3]) : "r"(saddr));
}
static __device__ __forceinline__ void ldsm4t(uint32_t* r, uint32_t saddr) {
    asm volatile("ldmatrix.sync.aligned.m8n8.x4.trans.shared.b16 {%0,%1,%2,%3}, [%4];"
                 : "=r"(r[0]), "=r"(r[1]), "=r"(r[2]), "=r"(r[3]) : "r"(saddr));
}
static __device__ __forceinline__ float ex2(float x) {
    float y; asm("ex2.approx.f32 %0, %1;" : "=f"(y) : "f"(x)); return y;
}

// ---------------------------------------------------------------------------
// fp32 -> fp16 convert, all 6 arrays in one launch (R8 variant).
// ---------------------------------------------------------------------------
__global__ void convert_h(const float4* __restrict__ s0, const float4* __restrict__ s1,
                          const float4* __restrict__ s2, const float4* __restrict__ s3,
                          const float4* __restrict__ s4, const float4* __restrict__ s5,
                          int n4x, int n4w)
{
    const int i = blockIdx.x * 256 + threadIdx.x;
    const int m = blockIdx.y;
    const int n4 = (m < 3) ? n4x : n4w;
    if (i >= n4) return;
    const float4* src = (m == 0) ? s0 : (m == 1) ? s1 : (m == 2) ? s2
                       : (m == 3) ? s3 : (m == 4) ? s4 : s5;
    uint2* dst = (m < 3) ? (uint2*)g_xh[m] : (uint2*)g_wh[m - 3];
    float4 v = src[i];
    dst[i] = make_uint2(pack2h(v.x, v.y), pack2h(v.z, v.w));
}

// ---------------------------------------------------------------------------
// Tensor-core GEMM (fp16, fp32 acc) — R8 config: CTA 128x128, 8 warps,
// K staged 64, triple-buffered cp.async ring, one sync per stage.
// row0 selects the M-row range (batch-pair split for stream overlap).
// ---------------------------------------------------------------------------
#define GST     144
#define GTILE   (128 * GST)
#define GSTAGE  (2 * GTILE)
#define GNST    (HH / 64)
#define GEMM_SMEM (3 * GSTAGE)

__global__ void __launch_bounds__(256, 2) gemm_mma(
    const float* __restrict__ bq, const float* __restrict__ bk, const float* __restrict__ bv,
    int row0)
{
    extern __shared__ char smc[];
    const int mat = blockIdx.z;
    const float* bias = (mat == 0) ? bq : ((mat == 1) ? bk : bv);

    const int tid  = threadIdx.x;
    const int lane = tid & 31;
    const int wid  = tid >> 5;
    const int wm   = wid & 1;
    const int wn   = wid >> 1;
    const int bm   = row0 + blockIdx.y * 128;
    const int bn   = blockIdx.x * 128;

    const __half* Ah = g_xh[mat] + (size_t)bm * HH;
    const __half* Bh = g_wh[mat] + (size_t)bn * HH;

    const uint32_t smem_base = smem_u32(smc);

    auto issue_stage = [&](int s, int buf) {
        const uint32_t sb = smem_base + (uint32_t)buf * GSTAGE;
        const int k0 = s * 64;
#pragma unroll
        for (int i = 0; i < 4; i++) {
            const int idx = tid + i * 256;
            const int row = idx >> 3;
            const int q   = idx & 7;
            const uint32_t so = (uint32_t)(row * GST + q * 16);
            const size_t   go = (size_t)row * HH + k0 + q * 8;
            cp16(sb + so, Ah + go);
            cp16(sb + GTILE + so, Bh + go);
        }
    };

    float acc[4][4][4];
#pragma unroll
    for (int i = 0; i < 4; i++)
#pragma unroll
        for (int j = 0; j < 4; j++)
#pragma unroll
            for (int k = 0; k < 4; k++) acc[i][j][k] = 0.f;

    issue_stage(0, 0); CP_COMMIT();
    issue_stage(1, 1); CP_COMMIT();

    const int arow = wm * 64 + ((lane >> 3) & 1) * 8 + (lane & 7);
    const int acol = (lane >> 4) * 8;
    const int brow = wn * 32 + (lane & 15);
    const int bcol = (lane >> 4) * 8;

    int cur = 0;
    for (int s = 0; s < GNST; s++) {
        if (s + 1 < GNST) { asm volatile("cp.async.wait_group 1;" ::: "memory"); }
        else              { asm volatile("cp.async.wait_group 0;" ::: "memory"); }
        __syncthreads();

        if (s + 2 < GNST) {
            int nb = cur + 2; if (nb >= 3) nb -= 3;
            issue_stage(s + 2, nb);
            CP_COMMIT();
        }

        const uint32_t sA = smem_base + (uint32_t)cur * GSTAGE;
        const uint32_t sB = sA + GTILE;

#pragma unroll
        for (int t = 0; t < 4; t++) {
            uint32_t Af[4][4], Bf[4][2];
#pragma unroll
            for (int mf = 0; mf < 4; mf++)
                ldsm4(Af[mf], sA + (arow + mf * 16) * GST + (t * 16 + acol) * 2);
#pragma unroll
            for (int np = 0; np < 2; np++) {
                uint32_t kh[4];
                ldsm4(kh, sB + (brow + np * 16) * GST + (t * 16 + bcol) * 2);
                Bf[2 * np][0]     = kh[0]; Bf[2 * np][1]     = kh[2];
                Bf[2 * np + 1][0] = kh[1]; Bf[2 * np + 1][1] = kh[3];
            }
#pragma unroll
            for (int mf = 0; mf < 4; mf++)
#pragma unroll
                for (int nf = 0; nf < 4; nf++)
                    mma_f16(acc[mf][nf], Af[mf], Bf[nf]);
        }

        cur = (cur + 1 == 3) ? 0 : cur + 1;
    }

    const float sc = (mat == 0) ? SCLQ : 1.0f;
    uint32_t* ph = (mat == 0) ? (uint32_t*)g_qh : ((mat == 1) ? (uint32_t*)g_kh : (uint32_t*)g_vh);

#pragma unroll
    for (int nf = 0; nf < 4; nf++) {
        const int col = bn + wn * 32 + nf * 8 + (lane & 3) * 2;
        const float2 bs = *(const float2*)&bias[col];
#pragma unroll
        for (int mf = 0; mf < 4; mf++) {
            const int row0w = bm + wm * 64 + mf * 16 + (lane >> 2);
            float v0 = fmaxf(acc[mf][nf][0] + bs.x, 0.f) * sc;
            float v1 = fmaxf(acc[mf][nf][1] + bs.y, 0.f) * sc;
            float v2 = fmaxf(acc[mf][nf][2] + bs.x, 0.f) * sc;
            float v3 = fmaxf(acc[mf][nf][3] + bs.y, 0.f) * sc;
            ph[((size_t)row0w * HH + col) >> 1]       = pack2h(v0, v1);
            ph[((size_t)(row0w + 8) * HH + col) >> 1] = pack2h(v2, v3);
        }
    }
}

// ---------------------------------------------------------------------------
// Tensor-core flash attention (R9 config, best measured): max-free softmax,
// kv-tile 64, fp16-acc QK^T (bit-exact repack), fp32-acc PV, 4 CTA/SM.
// b0 selects the batch range (batch-pair split for stream overlap).
// ---------------------------------------------------------------------------
#define QB      64
#define KRST    144
#define KVT     64
#define KVOFF   (KVT * KRST)
#define KBUF    (2 * KVOFF)
#define ATT_SMEM (2 * KBUF)
#define NKV     (SS / KVT)

__global__ void __launch_bounds__(128, 4) attn_tc(
    const float* __restrict__ masks,
    const float* __restrict__ query,
    float* __restrict__ out,
    int b0)
{
    extern __shared__ char sma[];
    const uint32_t smb = smem_u32(sma);

    const int b    = b0 + blockIdx.z;
    const int n    = blockIdx.y;
    const int q0   = blockIdx.x * QB;
    const int tid  = threadIdx.x;
    const int lane = tid & 31;
    const int wid  = tid >> 5;
    const int hc   = n * DHEAD;

#pragma unroll
    for (int i = 0; i < 4; i++) {
        const int idx = tid + i * 128;
        const int row = idx >> 3, qq = idx & 7;
        cp16(smb + row * KRST + qq * 16,
             g_qh + (size_t)(b * SS + q0 + row) * HH + hc + qq * 8);
    }
    CP_COMMIT();
    asm volatile("cp.async.wait_group 0;" ::: "memory");
    __syncthreads();

    uint32_t qh[4][4];
    {
        const int arow = wid * 16 + ((lane >> 3) & 1) * 8 + (lane & 7);
        const int acol = (lane >> 4) * 8;
#pragma unroll
        for (int t = 0; t < 4; t++)
            ldsm4(qh[t], smb + arow * KRST + (16 * t + acol) * 2);
    }
    __syncthreads();

    auto issue_kv = [&](int s) {
        const uint32_t sb = smb + (uint32_t)((s & 1) * KBUF);
        const size_t tokbase = (size_t)(b * SS + s * KVT);
#pragma unroll
        for (int i = 0; i < 4; i++) {
            const int idx = tid + i * 128;
            const int row = idx >> 3, qq = idx & 7;
            const uint32_t soff = row * KRST + qq * 16;
            const size_t goff = (tokbase + row) * HH + hc + qq * 8;
            cp16(sb + soff, g_kh + goff);
            cp16(sb + KVOFF + soff, g_vh + goff);
        }
    };
    issue_kv(0); CP_COMMIT();
    issue_kv(1); CP_COMMIT();

    float O[8][4];
    float l0 = 0.f, l1 = 0.f;
#pragma unroll
    for (int i = 0; i < 8; i++)
#pragma unroll
        for (int j = 0; j < 4; j++) O[i][j] = 0.f;

    const int brow = lane & 15;
    const int bcol = (lane >> 4) * 8;

    for (int kb = 0; kb < NKV; kb++) {
        if (kb + 1 < NKV) { asm volatile("cp.async.wait_group 1;" ::: "memory"); }
        else              { asm volatile("cp.async.wait_group 0;" ::: "memory"); }
        __syncthreads();

        const uint32_t sb = smb + (uint32_t)((kb & 1) * KBUF);

        uint32_t Sh[8][2];
#pragma unroll
        for (int i = 0; i < 8; i++) { Sh[i][0] = 0u; Sh[i][1] = 0u; }

#pragma unroll
        for (int t = 0; t < 4; t++) {
#pragma unroll
            for (int j = 0; j < 4; j++) {
                uint32_t kh[4], bf[2];
                ldsm4(kh, sb + (16 * j + brow) * KRST + (16 * t + bcol) * 2);
                bf[0] = kh[0]; bf[1] = kh[2];
                mma_f16h(Sh[2 * j], qh[t], bf);
                bf[0] = kh[1]; bf[1] = kh[3];
                mma_f16h(Sh[2 * j + 1], qh[t], bf);
            }
        }

#pragma unroll
        for (int i = 0; i < 8; i++) {
            float2 a = unpack2h(Sh[i][0]);
            float2 c = unpack2h(Sh[i][1]);
            float e0 = ex2(a.x), e1 = ex2(a.y);
            float e2 = ex2(c.x), e3 = ex2(c.y);
            l0 += e0 + e1;
            l1 += e2 + e3;
            Sh[i][0] = pack2h(e0, e1);
            Sh[i][1] = pack2h(e2, e3);
        }

#pragma unroll
        for (int i = 0; i < 4; i++) {
            uint32_t Pa4[4] = {Sh[2 * i][0], Sh[2 * i][1],
                               Sh[2 * i + 1][0], Sh[2 * i + 1][1]};
#pragma unroll
            for (int t4 = 0; t4 < 4; t4++) {
                uint32_t v[4];
                ldsm4t(v, sb + KVOFF + (16 * i + brow) * KRST + (16 * t4 + bcol) * 2);
                mma_f16(O[2 * t4], Pa4, v);
                mma_f16(O[2 * t4 + 1], Pa4, v + 2);
            }
        }

        __syncthreads();
        if (kb + 2 < NKV) { issue_kv(kb + 2); CP_COMMIT(); }
    }

    l0 += __shfl_xor_sync(0xffffffffu, l0, 1);
    l0 += __shfl_xor_sync(0xffffffffu, l0, 2);
    l1 += __shfl_xor_sync(0xffffffffu, l1, 1);
    l1 += __shfl_xor_sync(0xffffffffu, l1, 2);

    const int qr0 = q0 + wid * 16 + (lane >> 2);
    const int qr1 = qr0 + 8;
    const float inv0 = masks[b * SS + qr0] / l0;
    const float inv1 = masks[b * SS + qr1] / l1;
#pragma unroll
    for (int nf = 0; nf < 8; nf++) {
        const int col = hc + nf * 8 + (lane & 3) * 2;
        const size_t o0 = (size_t)(b * SS + qr0) * HH + col;
        const size_t o1 = (size_t)(b * SS + qr1) * HH + col;
        float2 r0 = *(const float2*)&query[o0];
        float2 r1 = *(const float2*)&query[o1];
        r0.x = fmaf(O[nf][0], inv0, r0.x);
        r0.y = fmaf(O[nf][1], inv0, r0.y);
        r1.x = fmaf(O[nf][2], inv1, r1.x);
        r1.y = fmaf(O[nf][3], inv1, r1.y);
        *(float2*)&out[o0] = r0;
        *(float2*)&out[o1] = r1;
    }
}

// ---------------------------------------------------------------------------
// Launch: convert -> GEMM(b0,b1) -> [attn(b0,b1) || GEMM(b2,b3)] -> attn(b2,b3)
// via a forked stream joined with events (all capture-legal operations).
// ---------------------------------------------------------------------------
extern "C" void kernel_launch(void* const* d_in, const int* in_sizes, int n_in,
                              void* d_out, int out_size)
{
    (void)in_sizes; (void)n_in; (void)out_size;
    const float* query = (const float*)d_in[0];
    const float* key   = (const float*)d_in[1];
    const float* value = (const float*)d_in[2];
    const float* masks = (const float*)d_in[3];
    const float* Wq    = (const float*)d_in[4];
    const float* bq    = (const float*)d_in[5];
    const float* Wk    = (const float*)d_in[6];
    const float* bk    = (const float*)d_in[7];
    const float* Wv    = (const float*)d_in[8];
    const float* bv    = (const float*)d_in[9];
    float* out = (float*)d_out;

    cudaFuncSetAttribute(gemm_mma, cudaFuncAttributeMaxDynamicSharedMemorySize, GEMM_SMEM);
    cudaFuncSetAttribute(attn_tc, cudaFuncAttributeMaxDynamicSharedMemorySize, ATT_SMEM);

    cudaStream_t s2;
    cudaStreamCreateWithFlags(&s2, cudaStreamNonBlocking);
    cudaEvent_t e1, e2;
    cudaEventCreateWithFlags(&e1, cudaEventDisableTiming);
    cudaEventCreateWithFlags(&e2, cudaEventDisableTiming);

    const int n4x = MTOT * HH / 4;
    const int n4w = HH * HH / 4;
    convert_h<<<dim3(n4x / 256, 6), 256>>>(
        (const float4*)query, (const float4*)key, (const float4*)value,
        (const float4*)Wq, (const float4*)Wk, (const float4*)Wv, n4x, n4w);

    // GEMM for batches 0-1 (rows 0..2047)
    gemm_mma<<<dim3(HH / 128, 16, 3), 256, GEMM_SMEM>>>(bq, bk, bv, 0);
    cudaEventRecord(e1, 0);

    // Fork: GEMM for batches 2-3 on s2, overlapping attn for batches 0-1.
    cudaStreamWaitEvent(s2, e1, 0);
    gemm_mma<<<dim3(HH / 128, 16, 3), 256, GEMM_SMEM, s2>>>(bq, bk, bv, 2048);
    cudaEventRecord(e2, s2);

    attn_tc<<<dim3(SS / QB, NHEADS, 2), 128, ATT_SMEM>>>(masks, query, out, 0);

    // Join, then attn for batches 2-3.
    cudaStreamWaitEvent(0, e2, 0);
    attn_tc<<<dim3(SS / QB, NHEADS, 2), 128, ATT_SMEM>>>(masks, query, out, 2);

    cudaEventDestroy(e1);
    cudaEventDestroy(e2);
    cudaStreamDestroy(s2);
}

// round 11
// speedup vs baseline: 1.0536x; 1.0236x over previous
#include <cuda_runtime.h>
#include <cuda_fp16.h>
#include <cstdint>

// Problem constants
#define HH     1024
#define BB     4
#define SS     1024
#define NHEADS 16
#define DHEAD  64
#define MTOT   (BB * SS)

// fp16 copies of GEMM inputs.
__device__ __align__(16) __half g_xh[3][(size_t)MTOT * HH];
__device__ __align__(16) __half g_wh[3][(size_t)HH * HH];

// GEMM outputs for attention: Q (pre-scaled by 0.125*log2e), K, V in fp16.
__device__ __align__(16) __half g_qh[(size_t)MTOT * HH];
__device__ __align__(16) __half g_kh[(size_t)MTOT * HH];
__device__ __align__(16) __half g_vh[(size_t)MTOT * HH];

#define SCLQ 0.18033688f   // 0.125 * log2(e)

// ---------------------------------------------------------------------------
// helpers
// ---------------------------------------------------------------------------
static __device__ __forceinline__ uint32_t smem_u32(const void* p) {
    uint32_t a;
    asm("{ .reg .u64 t; cvta.to.shared.u64 t, %1; cvt.u32.u64 %0, t; }"
        : "=r"(a) : "l"(p));
    return a;
}
static __device__ __forceinline__ uint32_t pack2h(float x, float y) {
    __half2 h = __floats2half2_rn(x, y);
    return *reinterpret_cast<uint32_t*>(&h);
}
static __device__ __forceinline__ float2 unpack2h(uint32_t u) {
    __half2 h = *reinterpret_cast<__half2*>(&u);
    return __half22float2(h);
}
static __device__ __forceinline__ void cp16(uint32_t saddr, const void* g) {
    asm volatile("cp.async.cg.shared.global [%0], [%1], 16;"
                 :: "r"(saddr), "l"(g) : "memory");
}
#define CP_COMMIT() asm volatile("cp.async.commit_group;" ::: "memory")

static __device__ __forceinline__ void mma_f16(float* c, const uint32_t* a, const uint32_t* b) {
    asm volatile(
        "mma.sync.aligned.m16n8k16.row.col.f32.f16.f16.f32 "
        "{%0,%1,%2,%3}, {%4,%5,%6,%7}, {%8,%9}, {%0,%1,%2,%3};"
        : "+f"(c[0]), "+f"(c[1]), "+f"(c[2]), "+f"(c[3])
        : "r"(a[0]), "r"(a[1]), "r"(a[2]), "r"(a[3]), "r"(b[0]), "r"(b[1]));
}
// fp16-accumulate variant (QK^T only — logits small, 4 k-steps)
static __device__ __forceinline__ void mma_f16h(uint32_t* c, const uint32_t* a, const uint32_t* b) {
    asm volatile(
        "mma.sync.aligned.m16n8k16.row.col.f16.f16.f16.f16 "
        "{%0,%1}, {%2,%3,%4,%5}, {%6,%7}, {%0,%1};"
        : "+r"(c[0]), "+r"(c[1])
        : "r"(a[0]), "r"(a[1]), "r"(a[2]), "r"(a[3]), "r"(b[0]), "r"(b[1]));
}
static __device__ __forceinline__ void ldsm4(uint32_t* r, uint32_t saddr) {
    asm volatile("ldmatrix.sync.aligned.m8n8.x4.shared.b16 {%0,%1,%2,%3}, [%4];"
                 : "=r"(r[0]), "=r"(r[1]), "=r"(r[2]), "=r"(r[3]) : "r"(saddr));
}
static __device__ __forceinline__ void ldsm4t(uint32_t* r, uint32_t saddr) {
    asm volatile("ldmatrix.sync.aligned.m8n8.x4.trans.shared.b16 {%0,%1,%2,%3}, [%4];"
                 : "=r"(r[0]), "=r"(r[1]), "=r"(r[2]), "=r"(r[3]) : "r"(saddr));
}
static __device__ __forceinline__ float ex2(float x) {
    float y; asm("ex2.approx.f32 %0, %1;" : "=f"(y) : "f"(x)); return y;
}

// ---------------------------------------------------------------------------
// fp32 -> fp16 convert for ONE projection's X and W, flat grid (no idle blocks).
// ---------------------------------------------------------------------------
__global__ void convert_pair(const float4* __restrict__ X, const float4* __restrict__ W,
                             int mat, int n4x, int n4w)
{
    const int i = blockIdx.x * 256 + threadIdx.x;
    if (i < n4x) {
        float4 v = X[i];
        ((uint2*)g_xh[mat])[i] = make_uint2(pack2h(v.x, v.y), pack2h(v.z, v.w));
    } else {
        const int j = i - n4x;
        if (j < n4w) {
            float4 v = W[j];
            ((uint2*)g_wh[mat])[j] = make_uint2(pack2h(v.x, v.y), pack2h(v.z, v.w));
        }
    }
}

// ---------------------------------------------------------------------------
// Tensor-core GEMM (fp16, fp32 acc) — R8 config (the 180.7us winner):
// CTA 128x128, 8 warps, K staged 64, triple-buffered cp.async ring,
// one __syncthreads per stage. `mat` selects projection (per-mat launches
// so converts for later mats can overlap gemm of earlier ones).
// ---------------------------------------------------------------------------
#define GST     144
#define GTILE   (128 * GST)
#define GSTAGE  (2 * GTILE)
#define GNST    (HH / 64)
#define GEMM_SMEM (3 * GSTAGE)

__global__ void __launch_bounds__(256, 2) gemm_mma(
    const float* __restrict__ bias, int mat)
{
    extern __shared__ char smc[];

    const int tid  = threadIdx.x;
    const int lane = tid & 31;
    const int wid  = tid >> 5;
    const int wm   = wid & 1;
    const int wn   = wid >> 1;
    const int bm   = blockIdx.y * 128;
    const int bn   = blockIdx.x * 128;

    const __half* Ah = g_xh[mat] + (size_t)bm * HH;
    const __half* Bh = g_wh[mat] + (size_t)bn * HH;

    const uint32_t smem_base = smem_u32(smc);

    auto issue_stage = [&](int s, int buf) {
        const uint32_t sb = smem_base + (uint32_t)buf * GSTAGE;
        const int k0 = s * 64;
#pragma unroll
        for (int i = 0; i < 4; i++) {
            const int idx = tid + i * 256;
            const int row = idx >> 3;
            const int q   = idx & 7;
            const uint32_t so = (uint32_t)(row * GST + q * 16);
            const size_t   go = (size_t)row * HH + k0 + q * 8;
            cp16(sb + so, Ah + go);
            cp16(sb + GTILE + so, Bh + go);
        }
    };

    float acc[4][4][4];
#pragma unroll
    for (int i = 0; i < 4; i++)
#pragma unroll
        for (int j = 0; j < 4; j++)
#pragma unroll
            for (int k = 0; k < 4; k++) acc[i][j][k] = 0.f;

    issue_stage(0, 0); CP_COMMIT();
    issue_stage(1, 1); CP_COMMIT();

    const int arow = wm * 64 + ((lane >> 3) & 1) * 8 + (lane & 7);
    const int acol = (lane >> 4) * 8;
    const int brow = wn * 32 + (lane & 15);
    const int bcol = (lane >> 4) * 8;

    int cur = 0;
    for (int s = 0; s < GNST; s++) {
        if (s + 1 < GNST) { asm volatile("cp.async.wait_group 1;" ::: "memory"); }
        else              { asm volatile("cp.async.wait_group 0;" ::: "memory"); }
        __syncthreads();

        if (s + 2 < GNST) {
            int nb = cur + 2; if (nb >= 3) nb -= 3;
            issue_stage(s + 2, nb);
            CP_COMMIT();
        }

        const uint32_t sA = smem_base + (uint32_t)cur * GSTAGE;
        const uint32_t sB = sA + GTILE;

#pragma unroll
        for (int t = 0; t < 4; t++) {
            uint32_t Af[4][4], Bf[4][2];
#pragma unroll
            for (int mf = 0; mf < 4; mf++)
                ldsm4(Af[mf], sA + (arow + mf * 16) * GST + (t * 16 + acol) * 2);
#pragma unroll
            for (int np = 0; np < 2; np++) {
                uint32_t kh[4];
                ldsm4(kh, sB + (brow + np * 16) * GST + (t * 16 + bcol) * 2);
                Bf[2 * np][0]     = kh[0]; Bf[2 * np][1]     = kh[2];
                Bf[2 * np + 1][0] = kh[1]; Bf[2 * np + 1][1] = kh[3];
            }
#pragma unroll
            for (int mf = 0; mf < 4; mf++)
#pragma unroll
                for (int nf = 0; nf < 4; nf++)
                    mma_f16(acc[mf][nf], Af[mf], Bf[nf]);
        }

        cur = (cur + 1 == 3) ? 0 : cur + 1;
    }

    const float sc = (mat == 0) ? SCLQ : 1.0f;
    uint32_t* ph = (mat == 0) ? (uint32_t*)g_qh : ((mat == 1) ? (uint32_t*)g_kh : (uint32_t*)g_vh);

#pragma unroll
    for (int nf = 0; nf < 4; nf++) {
        const int col = bn + wn * 32 + nf * 8 + (lane & 3) * 2;
        const float2 bs = *(const float2*)&bias[col];
#pragma unroll
        for (int mf = 0; mf < 4; mf++) {
            const int row0 = bm + wm * 64 + mf * 16 + (lane >> 2);
            float v0 = fmaxf(acc[mf][nf][0] + bs.x, 0.f) * sc;
            float v1 = fmaxf(acc[mf][nf][1] + bs.y, 0.f) * sc;
            float v2 = fmaxf(acc[mf][nf][2] + bs.x, 0.f) * sc;
            float v3 = fmaxf(acc[mf][nf][3] + bs.y, 0.f) * sc;
            ph[((size_t)row0 * HH + col) >> 1]       = pack2h(v0, v1);
            ph[((size_t)(row0 + 8) * HH + col) >> 1] = pack2h(v2, v3);
        }
    }
}

// ---------------------------------------------------------------------------
// Tensor-core flash attention — R8 exact (the 180.7us winner): max-free
// softmax, kv-tile 128 double-buffered, fp16-acc QK^T (bit-exact repack into
// P A-frags), fp32-acc PV, 3 CTA/SM.
// ---------------------------------------------------------------------------
#define QB      64
#define KRST    144
#define KBUF    18432
#define OFF_V   36864
#define ATT_SMEM 73728

__global__ void __launch_bounds__(128, 3) attn_tc(
    const float* __restrict__ masks,
    const float* __restrict__ query,
    float* __restrict__ out)
{
    extern __shared__ char sma[];
    const uint32_t smb = smem_u32(sma);

    const int b    = blockIdx.z;
    const int n    = blockIdx.y;
    const int q0   = blockIdx.x * QB;
    const int tid  = threadIdx.x;
    const int lane = tid & 31;
    const int wid  = tid >> 5;
    const int hc   = n * DHEAD;

#pragma unroll
    for (int i = 0; i < 4; i++) {
        const int idx = tid + i * 128;
        const int row = idx >> 3, qq = idx & 7;
        cp16(smb + row * KRST + qq * 16,
             g_qh + (size_t)(b * SS + q0 + row) * HH + hc + qq * 8);
    }
    CP_COMMIT();
    asm volatile("cp.async.wait_group 0;" ::: "memory");
    __syncthreads();

    uint32_t qh[4][4];
    {
        const int arow = wid * 16 + ((lane >> 3) & 1) * 8 + (lane & 7);
        const int acol = (lane >> 4) * 8;
#pragma unroll
        for (int t = 0; t < 4; t++)
            ldsm4(qh[t], smb + arow * KRST + (16 * t + acol) * 2);
    }
    __syncthreads();

    auto issue_kv = [&](int s) {
        const uint32_t sb = smb + (uint32_t)((s & 1) * KBUF);
        const size_t tokbase = (size_t)(b * SS + s * 128);
#pragma unroll
        for (int i = 0; i < 8; i++) {
            const int idx = tid + i * 128;
            const int row = idx >> 3, qq = idx & 7;
            const uint32_t soff = row * KRST + qq * 16;
            const size_t goff = (tokbase + row) * HH + hc + qq * 8;
            cp16(sb + soff, g_kh + goff);
            cp16(sb + OFF_V + soff, g_vh + goff);
        }
    };
    issue_kv(0); CP_COMMIT();
    issue_kv(1); CP_COMMIT();

    float O[8][4];
    float l0 = 0.f, l1 = 0.f;
#pragma unroll
    for (int i = 0; i < 8; i++)
#pragma unroll
        for (int j = 0; j < 4; j++) O[i][j] = 0.f;

    const int brow = lane & 15;
    const int bcol = (lane >> 4) * 8;

    for (int kb = 0; kb < SS / 128; kb++) {
        if (kb + 1 < SS / 128) { asm volatile("cp.async.wait_group 1;" ::: "memory"); }
        else                   { asm volatile("cp.async.wait_group 0;" ::: "memory"); }
        __syncthreads();

        const uint32_t sb = smb + (uint32_t)((kb & 1) * KBUF);

        uint32_t Sh[8][2];
#pragma unroll
        for (int i = 0; i < 8; i++) { Sh[i][0] = 0u; Sh[i][1] = 0u; }

#pragma unroll
        for (int t = 0; t < 4; t++) {
#pragma unroll
            for (int j = 0; j < 4; j++) {
                uint32_t kh[4], bf[2];
                ldsm4(kh, sb + (16 * j + brow) * KRST + (16 * t + bcol) * 2);
                bf[0] = kh[0]; bf[1] = kh[2];
                mma_f16h(Sh[2 * j], qh[t], bf);
                bf[0] = kh[1]; bf[1] = kh[3];
                mma_f16h(Sh[2 * j + 1], qh[t], bf);
            }
        }

        // second 64 kv rows of this 128-tile
        uint32_t Sh2[8][2];
#pragma unroll
        for (int i = 0; i < 8; i++) { Sh2[i][0] = 0u; Sh2[i][1] = 0u; }
#pragma unroll
        for (int t = 0; t < 4; t++) {
#pragma unroll
            for (int j = 4; j < 8; j++) {
                uint32_t kh[4], bf[2];
                ldsm4(kh, sb + (16 * j + brow) * KRST + (16 * t + bcol) * 2);
                bf[0] = kh[0]; bf[1] = kh[2];
                mma_f16h(Sh2[2 * (j - 4)], qh[t], bf);
                bf[0] = kh[1]; bf[1] = kh[3];
                mma_f16h(Sh2[2 * (j - 4) + 1], qh[t], bf);
            }
        }

#pragma unroll
        for (int i = 0; i < 8; i++) {
            float2 a = unpack2h(Sh[i][0]);
            float2 c = unpack2h(Sh[i][1]);
            float e0 = ex2(a.x), e1 = ex2(a.y);
            float e2 = ex2(c.x), e3 = ex2(c.y);
            l0 += e0 + e1;
            l1 += e2 + e3;
            Sh[i][0] = pack2h(e0, e1);
            Sh[i][1] = pack2h(e2, e3);

            float2 a2 = unpack2h(Sh2[i][0]);
            float2 c2 = unpack2h(Sh2[i][1]);
            float f0 = ex2(a2.x), f1 = ex2(a2.y);
            float f2 = ex2(c2.x), f3 = ex2(c2.y);
            l0 += f0 + f1;
            l1 += f2 + f3;
            Sh2[i][0] = pack2h(f0, f1);
            Sh2[i][1] = pack2h(f2, f3);
        }

#pragma unroll
        for (int i = 0; i < 4; i++) {
            uint32_t Pa4[4] = {Sh[2 * i][0], Sh[2 * i][1],
                               Sh[2 * i + 1][0], Sh[2 * i + 1][1]};
#pragma unroll
            for (int t4 = 0; t4 < 4; t4++) {
                uint32_t v[4];
                ldsm4t(v, sb + OFF_V + (16 * i + brow) * KRST + (16 * t4 + bcol) * 2);
                mma_f16(O[2 * t4], Pa4, v);
                mma_f16(O[2 * t4 + 1], Pa4, v + 2);
            }
        }
#pragma unroll
        for (int i = 0; i < 4; i++) {
            uint32_t Pa4[4] = {Sh2[2 * i][0], Sh2[2 * i][1],
                               Sh2[2 * i + 1][0], Sh2[2 * i + 1][1]};
#pragma unroll
            for (int t4 = 0; t4 < 4; t4++) {
                uint32_t v[4];
                ldsm4t(v, sb + OFF_V + (16 * (i + 4) + brow) * KRST + (16 * t4 + bcol) * 2);
                mma_f16(O[2 * t4], Pa4, v);
                mma_f16(O[2 * t4 + 1], Pa4, v + 2);
            }
        }

        __syncthreads();
        if (kb + 2 < SS / 128) { issue_kv(kb + 2); CP_COMMIT(); }
    }

    l0 += __shfl_xor_sync(0xffffffffu, l0, 1);
    l0 += __shfl_xor_sync(0xffffffffu, l0, 2);
    l1 += __shfl_xor_sync(0xffffffffu, l1, 1);
    l1 += __shfl_xor_sync(0xffffffffu, l1, 2);

    const int qr0 = q0 + wid * 16 + (lane >> 2);
    const int qr1 = qr0 + 8;
    const float inv0 = masks[b * SS + qr0] / l0;
    const float inv1 = masks[b * SS + qr1] / l1;
#pragma unroll
    for (int nf = 0; nf < 8; nf++) {
        const int col = hc + nf * 8 + (lane & 3) * 2;
        const size_t o0 = (size_t)(b * SS + qr0) * HH + col;
        const size_t o1 = (size_t)(b * SS + qr1) * HH + col;
        float2 r0 = *(const float2*)&query[o0];
        float2 r1 = *(const float2*)&query[o1];
        r0.x = fmaf(O[nf][0], inv0, r0.x);
        r0.y = fmaf(O[nf][1], inv0, r0.y);
        r1.x = fmaf(O[nf][2], inv1, r1.x);
        r1.y = fmaf(O[nf][3], inv1, r1.y);
        *(float2*)&out[o0] = r0;
        *(float2*)&out[o1] = r1;
    }
}

// ---------------------------------------------------------------------------
// Launch: convert(q) -> [ gemm(q) || convert(k),convert(v) on s2 ]
//         -> gemm(k) -> gemm(v) -> attn
// Convert (memory-bound) hides under gemm(q) (tensor-bound): complementary
// resources, so the overlap is genuinely additive.
// ---------------------------------------------------------------------------
extern "C" void kernel_launch(void* const* d_in, const int* in_sizes, int n_in,
                              void* d_out, int out_size)
{
    (void)in_sizes; (void)n_in; (void)out_size;
    const float* query = (const float*)d_in[0];
    const float* key   = (const float*)d_in[1];
    const float* value = (const float*)d_in[2];
    const float* masks = (const float*)d_in[3];
    const float* Wq    = (const float*)d_in[4];
    const float* bq    = (const float*)d_in[5];
    const float* Wk    = (const float*)d_in[6];
    const float* bk    = (const float*)d_in[7];
    const float* Wv    = (const float*)d_in[8];
    const float* bv    = (const float*)d_in[9];
    float* out = (float*)d_out;

    cudaFuncSetAttribute(gemm_mma, cudaFuncAttributeMaxDynamicSharedMemorySize, GEMM_SMEM);
    cudaFuncSetAttribute(attn_tc, cudaFuncAttributeMaxDynamicSharedMemorySize, ATT_SMEM);

    cudaStream_t s2;
    cudaStreamCreateWithFlags(&s2, cudaStreamNonBlocking);
    cudaEvent_t eq, ekv;
    cudaEventCreateWithFlags(&eq, cudaEventDisableTiming);
    cudaEventCreateWithFlags(&ekv, cudaEventDisableTiming);

    const int n4x = MTOT * HH / 4;     // 1,048,576 float4
    const int n4w = HH * HH / 4;       //   262,144 float4
    const int cblocks = (n4x + n4w) / 256;   // 5120, exact

    // convert q inputs first (critical path for gemm q)
    convert_pair<<<cblocks, 256>>>((const float4*)query, (const float4*)Wq, 0, n4x, n4w);
    cudaEventRecord(eq, 0);

    // k/v converts on s2, overlapping gemm(q)
    cudaStreamWaitEvent(s2, eq, 0);
    convert_pair<<<cblocks, 256, 0, s2>>>((const float4*)key,   (const float4*)Wk, 1, n4x, n4w);
    convert_pair<<<cblocks, 256, 0, s2>>>((const float4*)value, (const float4*)Wv, 2, n4x, n4w);
    cudaEventRecord(ekv, s2);

    gemm_mma<<<dim3(HH / 128, MTOT / 128), 256, GEMM_SMEM>>>(bq, 0);

    cudaStreamWaitEvent(0, ekv, 0);
    gemm_mma<<<dim3(HH / 128, MTOT / 128), 256, GEMM_SMEM>>>(bk, 1);
    gemm_mma<<<dim3(HH / 128, MTOT / 128), 256, GEMM_SMEM>>>(bv, 2);

    attn_tc<<<dim3(SS / QB, NHEADS, BB), 128, ATT_SMEM>>>(masks, query, out);

    cudaEventDestroy(eq);
    cudaEventDestroy(ekv);
    cudaStreamDestroy(s2);
}

// round 12
// speedup vs baseline: 1.1531x; 1.0945x over previous
#include <cuda_runtime.h>
#include <cuda_fp16.h>
#include <cstdint>

// Problem constants
#define HH     1024
#define BB     4
#define SS     1024
#define NHEADS 16
#define DHEAD  64
#define MTOT   (BB * SS)

// fp16 copies of GEMM inputs.
__device__ __align__(16) __half g_xh[3][(size_t)MTOT * HH];
__device__ __align__(16) __half g_wh[3][(size_t)HH * HH];

// GEMM outputs for attention: Q (pre-scaled by 0.125*log2e), K, V in fp16.
__device__ __align__(16) __half g_qh[(size_t)MTOT * HH];
__device__ __align__(16) __half g_kh[(size_t)MTOT * HH];
__device__ __align__(16) __half g_vh[(size_t)MTOT * HH];

#define SCLQ 0.18033688f   // 0.125 * log2(e)

// ---------------------------------------------------------------------------
// helpers
// ---------------------------------------------------------------------------
static __device__ __forceinline__ uint32_t smem_u32(const void* p) {
    uint32_t a;
    asm("{ .reg .u64 t; cvta.to.shared.u64 t, %1; cvt.u32.u64 %0, t; }"
        : "=r"(a) : "l"(p));
    return a;
}
static __device__ __forceinline__ uint32_t pack2h(float x, float y) {
    __half2 h = __floats2half2_rn(x, y);
    return *reinterpret_cast<uint32_t*>(&h);
}
static __device__ __forceinline__ float2 unpack2h(uint32_t u) {
    __half2 h = *reinterpret_cast<__half2*>(&u);
    return __half22float2(h);
}
static __device__ __forceinline__ void cp16(uint32_t saddr, const void* g) {
    asm volatile("cp.async.cg.shared.global [%0], [%1], 16;"
                 :: "r"(saddr), "l"(g) : "memory");
}
#define CP_COMMIT() asm volatile("cp.async.commit_group;" ::: "memory")

static __device__ __forceinline__ void mma_f16(float* c, const uint32_t* a, const uint32_t* b) {
    asm volatile(
        "mma.sync.aligned.m16n8k16.row.col.f32.f16.f16.f32 "
        "{%0,%1,%2,%3}, {%4,%5,%6,%7}, {%8,%9}, {%0,%1,%2,%3};"
        : "+f"(c[0]), "+f"(c[1]), "+f"(c[2]), "+f"(c[3])
        : "r"(a[0]), "r"(a[1]), "r"(a[2]), "r"(a[3]), "r"(b[0]), "r"(b[1]));
}
// fp16-accumulate variant (QK^T only — logits small, 4 k-steps)
static __device__ __forceinline__ void mma_f16h(uint32_t* c, const uint32_t* a, const uint32_t* b) {
    asm volatile(
        "mma.sync.aligned.m16n8k16.row.col.f16.f16.f16.f16 "
        "{%0,%1}, {%2,%3,%4,%5}, {%6,%7}, {%0,%1};"
        : "+r"(c[0]), "+r"(c[1])
        : "r"(a[0]), "r"(a[1]), "r"(a[2]), "r"(a[3]), "r"(b[0]), "r"(b[1]));
}
static __device__ __forceinline__ void ldsm4(uint32_t* r, uint32_t saddr) {
    asm volatile("ldmatrix.sync.aligned.m8n8.x4.shared.b16 {%0,%1,%2,%3}, [%4];"
                 : "=r"(r[0]), "=r"(r[1]), "=r"(r[2]), "=r"(r[3]) : "r"(saddr));
}
static __device__ __forceinline__ void ldsm4t(uint32_t* r, uint32_t saddr) {
    asm volatile("ldmatrix.sync.aligned.m8n8.x4.trans.shared.b16 {%0,%1,%2,%3}, [%4];"
                 : "=r"(r[0]), "=r"(r[1]), "=r"(r[2]), "=r"(r[3]) : "r"(saddr));
}
static __device__ __forceinline__ float ex2(float x) {
    float y; asm("ex2.approx.f32 %0, %1;" : "=f"(y) : "f"(x)); return y;
}

// ---------------------------------------------------------------------------
// fp32 -> fp16 convert for ONE projection's X and W, flat grid.
// ---------------------------------------------------------------------------
__global__ void convert_pair(const float4* __restrict__ X, const float4* __restrict__ W,
                             int mat, int n4x, int n4w)
{
    const int i = blockIdx.x * 256 + threadIdx.x;
    if (i < n4x) {
        float4 v = X[i];
        ((uint2*)g_xh[mat])[i] = make_uint2(pack2h(v.x, v.y), pack2h(v.z, v.w));
    } else {
        const int j = i - n4x;
        if (j < n4w) {
            float4 v = W[j];
            ((uint2*)g_wh[mat])[j] = make_uint2(pack2h(v.x, v.y), pack2h(v.z, v.w));
        }
    }
}

// ---------------------------------------------------------------------------
// Tensor-core GEMM (fp16, fp32 acc) — R8 champion config, byte-identical
// mainloop: CTA 128x128, 8 warps, K staged 64, triple-buffered cp.async
// ring, one __syncthreads per stage. One launch per projection; the three
// launches run CONCURRENTLY on separate streams so their waves pack like
// the fused launch while converts hide under earlier gemms.
// ---------------------------------------------------------------------------
#define GST     144
#define GTILE   (128 * GST)
#define GSTAGE  (2 * GTILE)
#define GNST    (HH / 64)
#define GEMM_SMEM (3 * GSTAGE)

__global__ void __launch_bounds__(256, 2) gemm_mma(
    const float* __restrict__ bias, int mat)
{
    extern __shared__ char smc[];

    const int tid  = threadIdx.x;
    const int lane = tid & 31;
    const int wid  = tid >> 5;
    const int wm   = wid & 1;
    const int wn   = wid >> 1;
    const int bm   = blockIdx.y * 128;
    const int bn   = blockIdx.x * 128;

    const __half* Ah = g_xh[mat] + (size_t)bm * HH;
    const __half* Bh = g_wh[mat] + (size_t)bn * HH;

    const uint32_t smem_base = smem_u32(smc);

    auto issue_stage = [&](int s, int buf) {
        const uint32_t sb = smem_base + (uint32_t)buf * GSTAGE;
        const int k0 = s * 64;
#pragma unroll
        for (int i = 0; i < 4; i++) {
            const int idx = tid + i * 256;
            const int row = idx >> 3;
            const int q   = idx & 7;
            const uint32_t so = (uint32_t)(row * GST + q * 16);
            const size_t   go = (size_t)row * HH + k0 + q * 8;
            cp16(sb + so, Ah + go);
            cp16(sb + GTILE + so, Bh + go);
        }
    };

    float acc[4][4][4];
#pragma unroll
    for (int i = 0; i < 4; i++)
#pragma unroll
        for (int j = 0; j < 4; j++)
#pragma unroll
            for (int k = 0; k < 4; k++) acc[i][j][k] = 0.f;

    issue_stage(0, 0); CP_COMMIT();
    issue_stage(1, 1); CP_COMMIT();

    const int arow = wm * 64 + ((lane >> 3) & 1) * 8 + (lane & 7);
    const int acol = (lane >> 4) * 8;
    const int brow = wn * 32 + (lane & 15);
    const int bcol = (lane >> 4) * 8;

    int cur = 0;
    for (int s = 0; s < GNST; s++) {
        if (s + 1 < GNST) { asm volatile("cp.async.wait_group 1;" ::: "memory"); }
        else              { asm volatile("cp.async.wait_group 0;" ::: "memory"); }
        __syncthreads();

        if (s + 2 < GNST) {
            int nb = cur + 2; if (nb >= 3) nb -= 3;
            issue_stage(s + 2, nb);
            CP_COMMIT();
        }

        const uint32_t sA = smem_base + (uint32_t)cur * GSTAGE;
        const uint32_t sB = sA + GTILE;

#pragma unroll
        for (int t = 0; t < 4; t++) {
            uint32_t Af[4][4], Bf[4][2];
#pragma unroll
            for (int mf = 0; mf < 4; mf++)
                ldsm4(Af[mf], sA + (arow + mf * 16) * GST + (t * 16 + acol) * 2);
#pragma unroll
            for (int np = 0; np < 2; np++) {
                uint32_t kh[4];
                ldsm4(kh, sB + (brow + np * 16) * GST + (t * 16 + bcol) * 2);
                Bf[2 * np][0]     = kh[0]; Bf[2 * np][1]     = kh[2];
                Bf[2 * np + 1][0] = kh[1]; Bf[2 * np + 1][1] = kh[3];
            }
#pragma unroll
            for (int mf = 0; mf < 4; mf++)
#pragma unroll
                for (int nf = 0; nf < 4; nf++)
                    mma_f16(acc[mf][nf], Af[mf], Bf[nf]);
        }

        cur = (cur + 1 == 3) ? 0 : cur + 1;
    }

    const float sc = (mat == 0) ? SCLQ : 1.0f;
    uint32_t* ph = (mat == 0) ? (uint32_t*)g_qh : ((mat == 1) ? (uint32_t*)g_kh : (uint32_t*)g_vh);

#pragma unroll
    for (int nf = 0; nf < 4; nf++) {
        const int col = bn + wn * 32 + nf * 8 + (lane & 3) * 2;
        const float2 bs = *(const float2*)&bias[col];
#pragma unroll
        for (int mf = 0; mf < 4; mf++) {
            const int row0 = bm + wm * 64 + mf * 16 + (lane >> 2);
            float v0 = fmaxf(acc[mf][nf][0] + bs.x, 0.f) * sc;
            float v1 = fmaxf(acc[mf][nf][1] + bs.y, 0.f) * sc;
            float v2 = fmaxf(acc[mf][nf][2] + bs.x, 0.f) * sc;
            float v3 = fmaxf(acc[mf][nf][3] + bs.y, 0.f) * sc;
            ph[((size_t)row0 * HH + col) >> 1]       = pack2h(v0, v1);
            ph[((size_t)(row0 + 8) * HH + col) >> 1] = pack2h(v2, v3);
        }
    }
}

// ---------------------------------------------------------------------------
// Tensor-core flash attention — R8 champion, byte-identical: max-free
// softmax, kv-tile 64, fp16-acc QK^T (bit-exact repack into P A-frags),
// fp32-acc PV, deferred l-reduction, 4 CTA/SM.
// ---------------------------------------------------------------------------
#define QB      64
#define KRST    144
#define KVT     64
#define KVOFF   (KVT * KRST)
#define KBUF    (2 * KVOFF)
#define ATT_SMEM (2 * KBUF)
#define NKV     (SS / KVT)

__global__ void __launch_bounds__(128, 4) attn_tc(
    const float* __restrict__ masks,
    const float* __restrict__ query,
    float* __restrict__ out)
{
    extern __shared__ char sma[];
    const uint32_t smb = smem_u32(sma);

    const int b    = blockIdx.z;
    const int n    = blockIdx.y;
    const int q0   = blockIdx.x * QB;
    const int tid  = threadIdx.x;
    const int lane = tid & 31;
    const int wid  = tid >> 5;
    const int hc   = n * DHEAD;

#pragma unroll
    for (int i = 0; i < 4; i++) {
        const int idx = tid + i * 128;
        const int row = idx >> 3, qq = idx & 7;
        cp16(smb + row * KRST + qq * 16,
             g_qh + (size_t)(b * SS + q0 + row) * HH + hc + qq * 8);
    }
    CP_COMMIT();
    asm volatile("cp.async.wait_group 0;" ::: "memory");
    __syncthreads();

    uint32_t qh[4][4];
    {
        const int arow = wid * 16 + ((lane >> 3) & 1) * 8 + (lane & 7);
        const int acol = (lane >> 4) * 8;
#pragma unroll
        for (int t = 0; t < 4; t++)
            ldsm4(qh[t], smb + arow * KRST + (16 * t + acol) * 2);
    }
    __syncthreads();

    auto issue_kv = [&](int s) {
        const uint32_t sb = smb + (uint32_t)((s & 1) * KBUF);
        const size_t tokbase = (size_t)(b * SS + s * KVT);
#pragma unroll
        for (int i = 0; i < 4; i++) {
            const int idx = tid + i * 128;
            const int row = idx >> 3, qq = idx & 7;
            const uint32_t soff = row * KRST + qq * 16;
            const size_t goff = (tokbase + row) * HH + hc + qq * 8;
            cp16(sb + soff, g_kh + goff);
            cp16(sb + KVOFF + soff, g_vh + goff);
        }
    };
    issue_kv(0); CP_COMMIT();
    issue_kv(1); CP_COMMIT();

    float O[8][4];
    float l0 = 0.f, l1 = 0.f;
#pragma unroll
    for (int i = 0; i < 8; i++)
#pragma unroll
        for (int j = 0; j < 4; j++) O[i][j] = 0.f;

    const int brow = lane & 15;
    const int bcol = (lane >> 4) * 8;

    for (int kb = 0; kb < NKV; kb++) {
        if (kb + 1 < NKV) { asm volatile("cp.async.wait_group 1;" ::: "memory"); }
        else              { asm volatile("cp.async.wait_group 0;" ::: "memory"); }
        __syncthreads();

        const uint32_t sb = smb + (uint32_t)((kb & 1) * KBUF);

        uint32_t Sh[8][2];
#pragma unroll
        for (int i = 0; i < 8; i++) { Sh[i][0] = 0u; Sh[i][1] = 0u; }

#pragma unroll
        for (int t = 0; t < 4; t++) {
#pragma unroll
            for (int j = 0; j < 4; j++) {
                uint32_t kh[4], bf[2];
                ldsm4(kh, sb + (16 * j + brow) * KRST + (16 * t + bcol) * 2);
                bf[0] = kh[0]; bf[1] = kh[2];
                mma_f16h(Sh[2 * j], qh[t], bf);
                bf[0] = kh[1]; bf[1] = kh[3];
                mma_f16h(Sh[2 * j + 1], qh[t], bf);
            }
        }

#pragma unroll
        for (int i = 0; i < 8; i++) {
            float2 a = unpack2h(Sh[i][0]);
            float2 c = unpack2h(Sh[i][1]);
            float e0 = ex2(a.x), e1 = ex2(a.y);
            float e2 = ex2(c.x), e3 = ex2(c.y);
            l0 += e0 + e1;
            l1 += e2 + e3;
            Sh[i][0] = pack2h(e0, e1);
            Sh[i][1] = pack2h(e2, e3);
        }

#pragma unroll
        for (int i = 0; i < 4; i++) {
            uint32_t Pa4[4] = {Sh[2 * i][0], Sh[2 * i][1],
                               Sh[2 * i + 1][0], Sh[2 * i + 1][1]};
#pragma unroll
            for (int t4 = 0; t4 < 4; t4++) {
                uint32_t v[4];
                ldsm4t(v, sb + KVOFF + (16 * i + brow) * KRST + (16 * t4 + bcol) * 2);
                mma_f16(O[2 * t4], Pa4, v);
                mma_f16(O[2 * t4 + 1], Pa4, v + 2);
            }
        }

        __syncthreads();
        if (kb + 2 < NKV) { issue_kv(kb + 2); CP_COMMIT(); }
    }

    l0 += __shfl_xor_sync(0xffffffffu, l0, 1);
    l0 += __shfl_xor_sync(0xffffffffu, l0, 2);
    l1 += __shfl_xor_sync(0xffffffffu, l1, 1);
    l1 += __shfl_xor_sync(0xffffffffu, l1, 2);

    const int qr0 = q0 + wid * 16 + (lane >> 2);
    const int qr1 = qr0 + 8;
    const float inv0 = masks[b * SS + qr0] / l0;
    const float inv1 = masks[b * SS + qr1] / l1;
#pragma unroll
    for (int nf = 0; nf < 8; nf++) {
        const int col = hc + nf * 8 + (lane & 3) * 2;
        const size_t o0 = (size_t)(b * SS + qr0) * HH + col;
        const size_t o1 = (size_t)(b * SS + qr1) * HH + col;
        float2 r0 = *(const float2*)&query[o0];
        float2 r1 = *(const float2*)&query[o1];
        r0.x = fmaf(O[nf][0], inv0, r0.x);
        r0.y = fmaf(O[nf][1], inv0, r0.y);
        r1.x = fmaf(O[nf][2], inv1, r1.x);
        r1.y = fmaf(O[nf][3], inv1, r1.y);
        *(float2*)&out[o0] = r0;
        *(float2*)&out[o1] = r1;
    }
}

// ---------------------------------------------------------------------------
// Launch topology — staggered converts, CONCURRENT gemms (waves pack across
// streams like the fused launch), join before attn:
//   main: conv_q → gemm_q ............................ join → attn
//   s2:   [conv_q done] conv_k → gemm_k ↗
//   s3:   [conv_k done] conv_v → gemm_v ↗
// ---------------------------------------------------------------------------
extern "C" void kernel_launch(void* const* d_in, const int* in_sizes, int n_in,
                              void* d_out, int out_size)
{
    (void)in_sizes; (void)n_in; (void)out_size;
    const float* query = (const float*)d_in[0];
    const float* key   = (const float*)d_in[1];
    const float* value = (const float*)d_in[2];
    const float* masks = (const float*)d_in[3];
    const float* Wq    = (const float*)d_in[4];
    const float* bq    = (const float*)d_in[5];
    const float* Wk    = (const float*)d_in[6];
    const float* bk    = (const float*)d_in[7];
    const float* Wv    = (const float*)d_in[8];
    const float* bv    = (const float*)d_in[9];
    float* out = (float*)d_out;

    cudaFuncSetAttribute(gemm_mma, cudaFuncAttributeMaxDynamicSharedMemorySize, GEMM_SMEM);
    cudaFuncSetAttribute(attn_tc, cudaFuncAttributeMaxDynamicSharedMemorySize, ATT_SMEM);

    cudaStream_t s2, s3;
    cudaStreamCreateWithFlags(&s2, cudaStreamNonBlocking);
    cudaStreamCreateWithFlags(&s3, cudaStreamNonBlocking);
    cudaEvent_t e_cq, e_ck, e_gk, e_gv;
    cudaEventCreateWithFlags(&e_cq, cudaEventDisableTiming);
    cudaEventCreateWithFlags(&e_ck, cudaEventDisableTiming);
    cudaEventCreateWithFlags(&e_gk, cudaEventDisableTiming);
    cudaEventCreateWithFlags(&e_gv, cudaEventDisableTiming);

    const int n4x = MTOT * HH / 4;          // 1,048,576 float4
    const int n4w = HH * HH / 4;            //   262,144 float4
    const int cblocks = (n4x + n4w) / 256;  // 5120, exact

    const dim3 ggrid(HH / 128, MTOT / 128); // (8, 32) = 256 CTAs per projection

    // main: conv_q -> gemm_q
    convert_pair<<<cblocks, 256>>>((const float4*)query, (const float4*)Wq, 0, n4x, n4w);
    cudaEventRecord(e_cq, 0);
    gemm_mma<<<ggrid, 256, GEMM_SMEM>>>(bq, 0);

    // s2: conv_k (hides under gemm_q) -> gemm_k (packs with gemm_q)
    cudaStreamWaitEvent(s2, e_cq, 0);
    convert_pair<<<cblocks, 256, 0, s2>>>((const float4*)key, (const float4*)Wk, 1, n4x, n4w);
    cudaEventRecord(e_ck, s2);
    gemm_mma<<<ggrid, 256, GEMM_SMEM, s2>>>(bk, 1);
    cudaEventRecord(e_gk, s2);

    // s3: conv_v -> gemm_v
    cudaStreamWaitEvent(s3, e_ck, 0);
    convert_pair<<<cblocks, 256, 0, s3>>>((const float4*)value, (const float4*)Wv, 2, n4x, n4w);
    gemm_mma<<<ggrid, 256, GEMM_SMEM, s3>>>(bv, 2);
    cudaEventRecord(e_gv, s3);

    // join all projections, then attention
    cudaStreamWaitEvent(0, e_gk, 0);
    cudaStreamWaitEvent(0, e_gv, 0);
    attn_tc<<<dim3(SS / QB, NHEADS, BB), 128, ATT_SMEM>>>(masks, query, out);

    cudaEventDestroy(e_cq);
    cudaEventDestroy(e_ck);
    cudaEventDestroy(e_gk);
    cudaEventDestroy(e_gv);
    cudaStreamDestroy(s2);
    cudaStreamDestroy(s3);
}

// round 13
// speedup vs baseline: 1.1979x; 1.0388x over previous
#include <cuda_runtime.h>
#include <cuda_fp16.h>
#include <cstdint>

// Problem constants
#define HH     1024
#define BB     4
#define SS     1024
#define NHEADS 16
#define DHEAD  64
#define MTOT   (BB * SS)

// fp16 copies of GEMM inputs.
__device__ __align__(16) __half g_xh[3][(size_t)MTOT * HH];
__device__ __align__(16) __half g_wh[3][(size_t)HH * HH];

// GEMM outputs for attention: Q (pre-scaled by 0.125*log2e), K, V in fp16.
__device__ __align__(16) __half g_qh[(size_t)MTOT * HH];
__device__ __align__(16) __half g_kh[(size_t)MTOT * HH];
__device__ __align__(16) __half g_vh[(size_t)MTOT * HH];

#define SCLQ 0.18033688f   // 0.125 * log2(e)

// ---------------------------------------------------------------------------
// helpers
// ---------------------------------------------------------------------------
static __device__ __forceinline__ uint32_t smem_u32(const void* p) {
    uint32_t a;
    asm("{ .reg .u64 t; cvta.to.shared.u64 t, %1; cvt.u32.u64 %0, t; }"
        : "=r"(a) : "l"(p));
    return a;
}
static __device__ __forceinline__ uint32_t pack2h(float x, float y) {
    __half2 h = __floats2half2_rn(x, y);
    return *reinterpret_cast<uint32_t*>(&h);
}
static __device__ __forceinline__ float2 unpack2h(uint32_t u) {
    __half2 h = *reinterpret_cast<__half2*>(&u);
    return __half22float2(h);
}
static __device__ __forceinline__ void cp16(uint32_t saddr, const void* g) {
    asm volatile("cp.async.cg.shared.global [%0], [%1], 16;"
                 :: "r"(saddr), "l"(g) : "memory");
}
#define CP_COMMIT() asm volatile("cp.async.commit_group;" ::: "memory")

static __device__ __forceinline__ void mma_f16(float* c, const uint32_t* a, const uint32_t* b) {
    asm volatile(
        "mma.sync.aligned.m16n8k16.row.col.f32.f16.f16.f32 "
        "{%0,%1,%2,%3}, {%4,%5,%6,%7}, {%8,%9}, {%0,%1,%2,%3};"
        : "+f"(c[0]), "+f"(c[1]), "+f"(c[2]), "+f"(c[3])
        : "r"(a[0]), "r"(a[1]), "r"(a[2]), "r"(a[3]), "r"(b[0]), "r"(b[1]));
}
// fp16-accumulate variant (QK^T only — logits small, 4 k-steps)
static __device__ __forceinline__ void mma_f16h(uint32_t* c, const uint32_t* a, const uint32_t* b) {
    asm volatile(
        "mma.sync.aligned.m16n8k16.row.col.f16.f16.f16.f16 "
        "{%0,%1}, {%2,%3,%4,%5}, {%6,%7}, {%0,%1};"
        : "+r"(c[0]), "+r"(c[1])
        : "r"(a[0]), "r"(a[1]), "r"(a[2]), "r"(a[3]), "r"(b[0]), "r"(b[1]));
}
static __device__ __forceinline__ void ldsm4(uint32_t* r, uint32_t saddr) {
    asm volatile("ldmatrix.sync.aligned.m8n8.x4.shared.b16 {%0,%1,%2,%3}, [%4];"
                 : "=r"(r[0]), "=r"(r[1]), "=r"(r[2]), "=r"(r[3]) : "r"(saddr));
}
static __device__ __forceinline__ void ldsm4t(uint32_t* r, uint32_t saddr) {
    asm volatile("ldmatrix.sync.aligned.m8n8.x4.trans.shared.b16 {%0,%1,%2,%3}, [%4];"
                 : "=r"(r[0]), "=r"(r[1]), "=r"(r[2]), "=r"(r[3]) : "r"(saddr));
}
static __device__ __forceinline__ float ex2(float x) {
    float y; asm("ex2.approx.f32 %0, %1;" : "=f"(y) : "f"(x)); return y;
}

// ---------------------------------------------------------------------------
// fp32 -> fp16 convert for ONE projection's X and W, flat grid.
// ---------------------------------------------------------------------------
__global__ void convert_pair(const float4* __restrict__ X, const float4* __restrict__ W,
                             int mat, int n4x, int n4w)
{
    const int i = blockIdx.x * 256 + threadIdx.x;
    if (i < n4x) {
        float4 v = X[i];
        ((uint2*)g_xh[mat])[i] = make_uint2(pack2h(v.x, v.y), pack2h(v.z, v.w));
    } else {
        const int j = i - n4x;
        if (j < n4w) {
            float4 v = W[j];
            ((uint2*)g_wh[mat])[j] = make_uint2(pack2h(v.x, v.y), pack2h(v.z, v.w));
        }
    }
}

// ---------------------------------------------------------------------------
// Tensor-core GEMM (fp16, fp32 acc) — champion mainloop, byte-identical:
// CTA 128x128, 8 warps, K staged 64, triple-buffered cp.async ring, one
// __syncthreads per stage. bn0 = column offset (half-N launches so attention
// head-halves can start as soon as their columns are done).
// ---------------------------------------------------------------------------
#define GST     144
#define GTILE   (128 * GST)
#define GSTAGE  (2 * GTILE)
#define GNST    (HH / 64)
#define GEMM_SMEM (3 * GSTAGE)

__global__ void __launch_bounds__(256, 2) gemm_mma(
    const float* __restrict__ bias, int mat, int bn0)
{
    extern __shared__ char smc[];

    const int tid  = threadIdx.x;
    const int lane = tid & 31;
    const int wid  = tid >> 5;
    const int wm   = wid & 1;
    const int wn   = wid >> 1;
    const int bm   = blockIdx.y * 128;
    const int bn   = bn0 + blockIdx.x * 128;

    const __half* Ah = g_xh[mat] + (size_t)bm * HH;
    const __half* Bh = g_wh[mat] + (size_t)bn * HH;

    const uint32_t smem_base = smem_u32(smc);

    auto issue_stage = [&](int s, int buf) {
        const uint32_t sb = smem_base + (uint32_t)buf * GSTAGE;
        const int k0 = s * 64;
#pragma unroll
        for (int i = 0; i < 4; i++) {
            const int idx = tid + i * 256;
            const int row = idx >> 3;
            const int q   = idx & 7;
            const uint32_t so = (uint32_t)(row * GST + q * 16);
            const size_t   go = (size_t)row * HH + k0 + q * 8;
            cp16(sb + so, Ah + go);
            cp16(sb + GTILE + so, Bh + go);
        }
    };

    float acc[4][4][4];
#pragma unroll
    for (int i = 0; i < 4; i++)
#pragma unroll
        for (int j = 0; j < 4; j++)
#pragma unroll
            for (int k = 0; k < 4; k++) acc[i][j][k] = 0.f;

    issue_stage(0, 0); CP_COMMIT();
    issue_stage(1, 1); CP_COMMIT();

    const int arow = wm * 64 + ((lane >> 3) & 1) * 8 + (lane & 7);
    const int acol = (lane >> 4) * 8;
    const int brow = wn * 32 + (lane & 15);
    const int bcol = (lane >> 4) * 8;

    int cur = 0;
    for (int s = 0; s < GNST; s++) {
        if (s + 1 < GNST) { asm volatile("cp.async.wait_group 1;" ::: "memory"); }
        else              { asm volatile("cp.async.wait_group 0;" ::: "memory"); }
        __syncthreads();

        if (s + 2 < GNST) {
            int nb = cur + 2; if (nb >= 3) nb -= 3;
            issue_stage(s + 2, nb);
            CP_COMMIT();
        }

        const uint32_t sA = smem_base + (uint32_t)cur * GSTAGE;
        const uint32_t sB = sA + GTILE;

#pragma unroll
        for (int t = 0; t < 4; t++) {
            uint32_t Af[4][4], Bf[4][2];
#pragma unroll
            for (int mf = 0; mf < 4; mf++)
                ldsm4(Af[mf], sA + (arow + mf * 16) * GST + (t * 16 + acol) * 2);
#pragma unroll
            for (int np = 0; np < 2; np++) {
                uint32_t kh[4];
                ldsm4(kh, sB + (brow + np * 16) * GST + (t * 16 + bcol) * 2);
                Bf[2 * np][0]     = kh[0]; Bf[2 * np][1]     = kh[2];
                Bf[2 * np + 1][0] = kh[1]; Bf[2 * np + 1][1] = kh[3];
            }
#pragma unroll
            for (int mf = 0; mf < 4; mf++)
#pragma unroll
                for (int nf = 0; nf < 4; nf++)
                    mma_f16(acc[mf][nf], Af[mf], Bf[nf]);
        }

        cur = (cur + 1 == 3) ? 0 : cur + 1;
    }

    const float sc = (mat == 0) ? SCLQ : 1.0f;
    uint32_t* ph = (mat == 0) ? (uint32_t*)g_qh : ((mat == 1) ? (uint32_t*)g_kh : (uint32_t*)g_vh);

#pragma unroll
    for (int nf = 0; nf < 4; nf++) {
        const int col = bn + wn * 32 + nf * 8 + (lane & 3) * 2;
        const float2 bs = *(const float2*)&bias[col];
#pragma unroll
        for (int mf = 0; mf < 4; mf++) {
            const int row0 = bm + wm * 64 + mf * 16 + (lane >> 2);
            float v0 = fmaxf(acc[mf][nf][0] + bs.x, 0.f) * sc;
            float v1 = fmaxf(acc[mf][nf][1] + bs.y, 0.f) * sc;
            float v2 = fmaxf(acc[mf][nf][2] + bs.x, 0.f) * sc;
            float v3 = fmaxf(acc[mf][nf][3] + bs.y, 0.f) * sc;
            ph[((size_t)row0 * HH + col) >> 1]       = pack2h(v0, v1);
            ph[((size_t)(row0 + 8) * HH + col) >> 1] = pack2h(v2, v3);
        }
    }
}

// ---------------------------------------------------------------------------
// Tensor-core flash attention — champion config, byte-identical mainloop:
// max-free softmax, kv-tile 64, fp16-acc QK^T (bit-exact repack), fp32-acc
// PV, deferred l-reduction, 4 CTA/SM. n0 = head offset (half launches).
// ---------------------------------------------------------------------------
#define QB      64
#define KRST    144
#define KVT     64
#define KVOFF   (KVT * KRST)
#define KBUF    (2 * KVOFF)
#define ATT_SMEM (2 * KBUF)
#define NKV     (SS / KVT)

__global__ void __launch_bounds__(128, 4) attn_tc(
    const float* __restrict__ masks,
    const float* __restrict__ query,
    float* __restrict__ out,
    int n0)
{
    extern __shared__ char sma[];
    const uint32_t smb = smem_u32(sma);

    const int b    = blockIdx.z;
    const int n    = n0 + blockIdx.y;
    const int q0   = blockIdx.x * QB;
    const int tid  = threadIdx.x;
    const int lane = tid & 31;
    const int wid  = tid >> 5;
    const int hc   = n * DHEAD;

#pragma unroll
    for (int i = 0; i < 4; i++) {
        const int idx = tid + i * 128;
        const int row = idx >> 3, qq = idx & 7;
        cp16(smb + row * KRST + qq * 16,
             g_qh + (size_t)(b * SS + q0 + row) * HH + hc + qq * 8);
    }
    CP_COMMIT();
    asm volatile("cp.async.wait_group 0;" ::: "memory");
    __syncthreads();

    uint32_t qh[4][4];
    {
        const int arow = wid * 16 + ((lane >> 3) & 1) * 8 + (lane & 7);
        const int acol = (lane >> 4) * 8;
#pragma unroll
        for (int t = 0; t < 4; t++)
            ldsm4(qh[t], smb + arow * KRST + (16 * t + acol) * 2);
    }
    __syncthreads();

    auto issue_kv = [&](int s) {
        const uint32_t sb = smb + (uint32_t)((s & 1) * KBUF);
        const size_t tokbase = (size_t)(b * SS + s * KVT);
#pragma unroll
        for (int i = 0; i < 4; i++) {
            const int idx = tid + i * 128;
            const int row = idx >> 3, qq = idx & 7;
            const uint32_t soff = row * KRST + qq * 16;
            const size_t goff = (tokbase + row) * HH + hc + qq * 8;
            cp16(sb + soff, g_kh + goff);
            cp16(sb + KVOFF + soff, g_vh + goff);
        }
    };
    issue_kv(0); CP_COMMIT();
    issue_kv(1); CP_COMMIT();

    float O[8][4];
    float l0 = 0.f, l1 = 0.f;
#pragma unroll
    for (int i = 0; i < 8; i++)
#pragma unroll
        for (int j = 0; j < 4; j++) O[i][j] = 0.f;

    const int brow = lane & 15;
    const int bcol = (lane >> 4) * 8;

    for (int kb = 0; kb < NKV; kb++) {
        if (kb + 1 < NKV) { asm volatile("cp.async.wait_group 1;" ::: "memory"); }
        else              { asm volatile("cp.async.wait_group 0;" ::: "memory"); }
        __syncthreads();

        const uint32_t sb = smb + (uint32_t)((kb & 1) * KBUF);

        uint32_t Sh[8][2];
#pragma unroll
        for (int i = 0; i < 8; i++) { Sh[i][0] = 0u; Sh[i][1] = 0u; }

#pragma unroll
        for (int t = 0; t < 4; t++) {
#pragma unroll
            for (int j = 0; j < 4; j++) {
                uint32_t kh[4], bf[2];
                ldsm4(kh, sb + (16 * j + brow) * KRST + (16 * t + bcol) * 2);
                bf[0] = kh[0]; bf[1] = kh[2];
                mma_f16h(Sh[2 * j], qh[t], bf);
                bf[0] = kh[1]; bf[1] = kh[3];
                mma_f16h(Sh[2 * j + 1], qh[t], bf);
            }
        }

#pragma unroll
        for (int i = 0; i < 8; i++) {
            float2 a = unpack2h(Sh[i][0]);
            float2 c = unpack2h(Sh[i][1]);
            float e0 = ex2(a.x), e1 = ex2(a.y);
            float e2 = ex2(c.x), e3 = ex2(c.y);
            l0 += e0 + e1;
            l1 += e2 + e3;
            Sh[i][0] = pack2h(e0, e1);
            Sh[i][1] = pack2h(e2, e3);
        }

#pragma unroll
        for (int i = 0; i < 4; i++) {
            uint32_t Pa4[4] = {Sh[2 * i][0], Sh[2 * i][1],
                               Sh[2 * i + 1][0], Sh[2 * i + 1][1]};
#pragma unroll
            for (int t4 = 0; t4 < 4; t4++) {
                uint32_t v[4];
                ldsm4t(v, sb + KVOFF + (16 * i + brow) * KRST + (16 * t4 + bcol) * 2);
                mma_f16(O[2 * t4], Pa4, v);
                mma_f16(O[2 * t4 + 1], Pa4, v + 2);
            }
        }

        __syncthreads();
        if (kb + 2 < NKV) { issue_kv(kb + 2); CP_COMMIT(); }
    }

    l0 += __shfl_xor_sync(0xffffffffu, l0, 1);
    l0 += __shfl_xor_sync(0xffffffffu, l0, 2);
    l1 += __shfl_xor_sync(0xffffffffu, l1, 1);
    l1 += __shfl_xor_sync(0xffffffffu, l1, 2);

    const int qr0 = q0 + wid * 16 + (lane >> 2);
    const int qr1 = qr0 + 8;
    const float inv0 = masks[b * SS + qr0] / l0;
    const float inv1 = masks[b * SS + qr1] / l1;
#pragma unroll
    for (int nf = 0; nf < 8; nf++) {
        const int col = hc + nf * 8 + (lane & 3) * 2;
        const size_t o0 = (size_t)(b * SS + qr0) * HH + col;
        const size_t o1 = (size_t)(b * SS + qr1) * HH + col;
        float2 r0 = *(const float2*)&query[o0];
        float2 r1 = *(const float2*)&query[o1];
        r0.x = fmaf(O[nf][0], inv0, r0.x);
        r0.y = fmaf(O[nf][1], inv0, r0.y);
        r1.x = fmaf(O[nf][2], inv1, r1.x);
        r1.y = fmaf(O[nf][3], inv1, r1.y);
        *(float2*)&out[o0] = r0;
        *(float2*)&out[o1] = r1;
    }
}

// ---------------------------------------------------------------------------
// Launch topology — column-half gemms + head-half attention for fine-grained
// overlap (attn_lo backfills SMs while hi-gemms drain):
//   main: conv_q → gemm_q_lo → gemm_q_hi ......... (join hi) attn_hi
//   s2:   (conv_q) conv_k → gemm_k_lo → gemm_k_hi
//   s3:   (conv_k) conv_v → gemm_v_lo → gemm_v_hi
//   s4:   (all lo done) attn_lo  → joined into main at the end
// ---------------------------------------------------------------------------
extern "C" void kernel_launch(void* const* d_in, const int* in_sizes, int n_in,
                              void* d_out, int out_size)
{
    (void)in_sizes; (void)n_in; (void)out_size;
    const float* query = (const float*)d_in[0];
    const float* key   = (const float*)d_in[1];
    const float* value = (const float*)d_in[2];
    const float* masks = (const float*)d_in[3];
    const float* Wq    = (const float*)d_in[4];
    const float* bq    = (const float*)d_in[5];
    const float* Wk    = (const float*)d_in[6];
    const float* bk    = (const float*)d_in[7];
    const float* Wv    = (const float*)d_in[8];
    const float* bv    = (const float*)d_in[9];
    float* out = (float*)d_out;

    cudaFuncSetAttribute(gemm_mma, cudaFuncAttributeMaxDynamicSharedMemorySize, GEMM_SMEM);
    cudaFuncSetAttribute(attn_tc, cudaFuncAttributeMaxDynamicSharedMemorySize, ATT_SMEM);

    cudaStream_t s2, s3, s4;
    cudaStreamCreateWithFlags(&s2, cudaStreamNonBlocking);
    cudaStreamCreateWithFlags(&s3, cudaStreamNonBlocking);
    cudaStreamCreateWithFlags(&s4, cudaStreamNonBlocking);
    cudaEvent_t e_cq, e_ck;
    cudaEvent_t e_qlo, e_klo, e_vlo, e_khi, e_vhi, e_alo;
    cudaEventCreateWithFlags(&e_cq,  cudaEventDisableTiming);
    cudaEventCreateWithFlags(&e_ck,  cudaEventDisableTiming);
    cudaEventCreateWithFlags(&e_qlo, cudaEventDisableTiming);
    cudaEventCreateWithFlags(&e_klo, cudaEventDisableTiming);
    cudaEventCreateWithFlags(&e_vlo, cudaEventDisableTiming);
    cudaEventCreateWithFlags(&e_khi, cudaEventDisableTiming);
    cudaEventCreateWithFlags(&e_vhi, cudaEventDisableTiming);
    cudaEventCreateWithFlags(&e_alo, cudaEventDisableTiming);

    const int n4x = MTOT * HH / 4;
    const int n4w = HH * HH / 4;
    const int cblocks = (n4x + n4w) / 256;

    const dim3 ghalf(HH / 256, MTOT / 128);   // (4, 32) = 128 CTAs per half

    // main: conv_q -> gemm_q lo, hi
    convert_pair<<<cblocks, 256>>>((const float4*)query, (const float4*)Wq, 0, n4x, n4w);
    cudaEventRecord(e_cq, 0);
    gemm_mma<<<ghalf, 256, GEMM_SMEM>>>(bq, 0, 0);
    cudaEventRecord(e_qlo, 0);
    gemm_mma<<<ghalf, 256, GEMM_SMEM>>>(bq, 0, 512);

    // s2: conv_k -> gemm_k lo, hi
    cudaStreamWaitEvent(s2, e_cq, 0);
    convert_pair<<<cblocks, 256, 0, s2>>>((const float4*)key, (const float4*)Wk, 1, n4x, n4w);
    cudaEventRecord(e_ck, s2);
    gemm_mma<<<ghalf, 256, GEMM_SMEM, s2>>>(bk, 1, 0);
    cudaEventRecord(e_klo, s2);
    gemm_mma<<<ghalf, 256, GEMM_SMEM, s2>>>(bk, 1, 512);
    cudaEventRecord(e_khi, s2);

    // s3: conv_v -> gemm_v lo, hi
    cudaStreamWaitEvent(s3, e_ck, 0);
    convert_pair<<<cblocks, 256, 0, s3>>>((const float4*)value, (const float4*)Wv, 2, n4x, n4w);
    gemm_mma<<<ghalf, 256, GEMM_SMEM, s3>>>(bv, 2, 0);
    cudaEventRecord(e_vlo, s3);
    gemm_mma<<<ghalf, 256, GEMM_SMEM, s3>>>(bv, 2, 512);
    cudaEventRecord(e_vhi, s3);

    // s4: attn for heads 0-7 as soon as lo columns of q/k/v are done
    cudaStreamWaitEvent(s4, e_qlo, 0);
    cudaStreamWaitEvent(s4, e_klo, 0);
    cudaStreamWaitEvent(s4, e_vlo, 0);
    attn_tc<<<dim3(SS / QB, NHEADS / 2, BB), 128, ATT_SMEM, s4>>>(masks, query, out, 0);
    cudaEventRecord(e_alo, s4);

    // main: attn for heads 8-15 after hi gemms; join attn_lo at the end
    cudaStreamWaitEvent(0, e_khi, 0);
    cudaStreamWaitEvent(0, e_vhi, 0);
    attn_tc<<<dim3(SS / QB, NHEADS / 2, BB), 128, ATT_SMEM>>>(masks, query, out, 8);
    cudaStreamWaitEvent(0, e_alo, 0);

    cudaEventDestroy(e_cq);
    cudaEventDestroy(e_ck);
    cudaEventDestroy(e_qlo);
    cudaEventDestroy(e_klo);
    cudaEventDestroy(e_vlo);
    cudaEventDestroy(e_khi);
    cudaEventDestroy(e_vhi);
    cudaEventDestroy(e_alo);
    cudaStreamDestroy(s2);
    cudaStreamDestroy(s3);
    cudaStreamDestroy(s4);
}